// round 1
// baseline (speedup 1.0000x reference)
#include <cuda_runtime.h>
#include <cuda_bf16.h>
#include <math.h>
#include <limits.h>

// ---------------- problem constants ----------------
#define Bb   2048
#define Ss   5
#define Nn   80
#define Ee   592
#define FX   8
#define FF   4
#define FE   8
#define Dd   8
#define Hh   800
#define SEQW (Nn*Dd + Ee*Dd)   // 5376
#define G3H  (3*Hh)            // 2400
#define MLP1 1280
#define OUTW (Ss*80)           // 400

// ---------------- scratch (device globals; no allocation allowed) ----------------
__device__ float g_seq[(size_t)Bb*Ss*SEQW];   // [10240, 5376]
__device__ float g_gi [(size_t)Bb*Ss*G3H];    // [10240, 2400]
__device__ float g_gh [(size_t)Bb*G3H];       // [2048, 2400]
__device__ float g_h  [(size_t)Bb*Hh];        // [2048, 800]
__device__ float g_y  [(size_t)Bb*Ss*Hh];     // [2048, 4000]
__device__ float g_z  [(size_t)Bb*MLP1];      // [2048, 1280]

// ---------------- GNN: one CTA per (b,s) graph ----------------
__global__ __launch_bounds__(256)
void gnn_kernel(const float* __restrict__ x,
                const int*   __restrict__ ei,
                const float* __restrict__ ef,
                const float* __restrict__ ea,
                const float* __restrict__ Wx,
                const float* __restrict__ We,
                const float* __restrict__ Wf,
                const float* __restrict__ Wedge,
                float* __restrict__ seq)
{
    const int g = blockIdx.x;
    const float* xg  = x  + (size_t)g * Nn * FX;
    const int*   src = ei + (size_t)g * 2 * Ee;
    const int*   dst = src + Ee;
    const float* efg = ef + (size_t)g * Ee * FF;
    const float* eag = ea + (size_t)g * Ee * FE;
    float* seqg = seq + (size_t)g * SEQW;

    __shared__ float sWx[FX*Dd];
    __shared__ float sWe[FE*Dd];
    __shared__ float sWf[FF*Dd];
    __shared__ float sWedge[(2*Dd+FE)*Dd];   // 24x8
    __shared__ float sagg[Nn*Dd];
    __shared__ float sxo [Nn*Dd];
    __shared__ float sea [Ee*FE];
    __shared__ int   ssrc[Ee], sdst[Ee];
    __shared__ int   sminv;

    const int tid = threadIdx.x;
    if (tid == 0) sminv = INT_MAX;
    if (tid < FX*Dd)  sWx[tid] = Wx[tid];
    if (tid < FE*Dd)  sWe[tid] = We[tid];
    if (tid < FF*Dd)  sWf[tid] = Wf[tid];
    if (tid < 192)    sWedge[tid] = Wedge[tid];
    for (int i = tid; i < Nn*Dd; i += 256) sagg[i] = 0.f;
    for (int i = tid; i < Ee*FE; i += 256) sea[i] = eag[i];
    __syncthreads();

    // min over src row (edge_index[b,s,0,:])
    int lm = INT_MAX;
    for (int e = tid; e < Ee; e += 256) lm = min(lm, src[e]);
    atomicMin(&sminv, lm);
    __syncthreads();
    const int minv = sminv;

    // edge messages + scatter-add
    for (int e = tid; e < Ee; e += 256) {
        int s = src[e] - minv;               // always in [0, Nn)
        int d = dst[e] - minv;
        if (d < 0) d += Nn;                  // JAX negative-index wrap
        ssrc[e] = s; sdst[e] = d;
        const float* eae = &sea[e*FE];
        float fe0 = efg[e*FF+0], fe1 = efg[e*FF+1], fe2 = efg[e*FF+2], fe3 = efg[e*FF+3];
        #pragma unroll
        for (int c = 0; c < Dd; c++) {
            float m = 0.f;
            #pragma unroll
            for (int k = 0; k < FE; k++) m += eae[k] * sWe[k*Dd + c];
            m += fe0*sWf[0*Dd+c] + fe1*sWf[1*Dd+c] + fe2*sWf[2*Dd+c] + fe3*sWf[3*Dd+c];
            m = fmaxf(m, 0.f);
            atomicAdd(&sagg[d*Dd + c], m);
        }
    }
    __syncthreads();

    // node update: x_out = x + relu(x@Wx + agg)
    for (int i = tid; i < Nn*Dd; i += 256) {
        int n = i / Dd, c = i % Dd;
        float t = sagg[i];
        #pragma unroll
        for (int k = 0; k < FX; k++) t += xg[n*FX + k] * sWx[k*Dd + c];
        float v = xg[i] + fmaxf(t, 0.f);
        sxo[i] = v;
        seqg[i] = v;
    }
    __syncthreads();

    // edge update: e_out = ea + relu([xo[src], xo[dst], ea] @ Wedge)
    for (int e = tid; e < Ee; e += 256) {
        const float* fs = &sxo[ssrc[e]*Dd];
        const float* fd = &sxo[sdst[e]*Dd];
        const float* eae = &sea[e*FE];
        #pragma unroll
        for (int c = 0; c < Dd; c++) {
            float v = 0.f;
            #pragma unroll
            for (int k = 0; k < Dd; k++) v += fs[k]  * sWedge[(k     )*Dd + c];
            #pragma unroll
            for (int k = 0; k < Dd; k++) v += fd[k]  * sWedge[(Dd + k)*Dd + c];
            #pragma unroll
            for (int k = 0; k < FE; k++) v += eae[k] * sWedge[(2*Dd+k)*Dd + c];
            seqg[Nn*Dd + e*Dd + c] = eae[c] + fmaxf(v, 0.f);
        }
    }
}

// ---------------- SGEMM: C[M,N] = A[M,K] @ op(B) + bias ----------------
// TB=true : B is [N,K] row-major (use B^T)   -> NT gemm
// TB=false: B is [K,N] row-major             -> NN gemm
// Requires K % 8 == 0 (true for 5376, 800, 4000, 1280).
#define BM 128
#define BN 128
#define BK 8
#define TM 8
#define TN 8

template <bool TB>
__global__ __launch_bounds__(256)
void sgemm(const float* __restrict__ A, const float* __restrict__ B,
           const float* __restrict__ bias, float* __restrict__ C,
           int M, int N, int K)
{
    __shared__ float As[BK][BM];
    __shared__ float Bs[BK][BN];

    const int tid = threadIdx.x;
    const int bm = blockIdx.y * BM;
    const int bn = blockIdx.x * BN;

    const int tr = (tid / 16) * TM;  // 0..120
    const int tc = (tid % 16) * TN;  // 0..120

    float acc[TM][TN];
    #pragma unroll
    for (int i = 0; i < TM; i++)
        #pragma unroll
        for (int j = 0; j < TN; j++) acc[i][j] = 0.f;

    const int arow = tid / 2;
    const int acol = (tid % 2) * 4;

    for (int k0 = 0; k0 < K; k0 += BK) {
        // A tile (128 rows x 8 k), float4 along K
        {
            float4 av = make_float4(0.f, 0.f, 0.f, 0.f);
            int gar = bm + arow;
            if (gar < M)
                av = *reinterpret_cast<const float4*>(A + (size_t)gar * K + k0 + acol);
            As[acol + 0][arow] = av.x;
            As[acol + 1][arow] = av.y;
            As[acol + 2][arow] = av.z;
            As[acol + 3][arow] = av.w;
        }
        // B tile
        if (TB) {
            // B [N,K]: 128 n-rows x 8 k
            float4 bv = make_float4(0.f, 0.f, 0.f, 0.f);
            int gbr = bn + arow;
            if (gbr < N)
                bv = *reinterpret_cast<const float4*>(B + (size_t)gbr * K + k0 + acol);
            Bs[acol + 0][arow] = bv.x;
            Bs[acol + 1][arow] = bv.y;
            Bs[acol + 2][arow] = bv.z;
            Bs[acol + 3][arow] = bv.w;
        } else {
            // B [K,N]: 8 k-rows x 128 n, float4 along N
            int brow = tid / 32;          // 0..7
            int bcol = (tid % 32) * 4;    // 0..124
            float4 bv = make_float4(0.f, 0.f, 0.f, 0.f);
            int gbc = bn + bcol;
            if (gbc < N)   // N % 4 == 0 for all call sites
                bv = *reinterpret_cast<const float4*>(B + (size_t)(k0 + brow) * N + gbc);
            *reinterpret_cast<float4*>(&Bs[brow][bcol]) = bv;
        }
        __syncthreads();

        #pragma unroll
        for (int k = 0; k < BK; k++) {
            float a[TM], b[TN];
            #pragma unroll
            for (int i = 0; i < TM; i++) a[i] = As[k][tr + i];
            #pragma unroll
            for (int j = 0; j < TN; j++) b[j] = Bs[k][tc + j];
            #pragma unroll
            for (int i = 0; i < TM; i++)
                #pragma unroll
                for (int j = 0; j < TN; j++)
                    acc[i][j] = fmaf(a[i], b[j], acc[i][j]);
        }
        __syncthreads();
    }

    #pragma unroll
    for (int i = 0; i < TM; i++) {
        int row = bm + tr + i;
        if (row >= M) continue;
        #pragma unroll
        for (int j = 0; j < TN; j++) {
            int col = bn + tc + j;
            if (col < N)
                C[(size_t)row * N + col] = acc[i][j] + bias[col];
        }
    }
}

// ---------------- GRU gates ----------------
__device__ __forceinline__ float sigmoidf(float v) { return 1.f / (1.f + expf(-v)); }

__global__ __launch_bounds__(256)
void gru_gate_kernel(const float* __restrict__ gi, const float* __restrict__ gh,
                     float* __restrict__ h, float* __restrict__ y, int t)
{
    int idx = blockIdx.x * blockDim.x + threadIdx.x;
    if (idx >= Bb * Hh) return;
    int b = idx / Hh, j = idx % Hh;
    const float* gir = gi + (size_t)(b * Ss + t) * G3H;
    const float* ghr = gh + (size_t)b * G3H;
    float ir = gir[j], iz = gir[Hh + j], in = gir[2*Hh + j];
    float hr = ghr[j], hz = ghr[Hh + j], hn = ghr[2*Hh + j];
    float r = sigmoidf(ir + hr);
    float z = sigmoidf(iz + hz);
    float n = tanhf(in + r * hn);
    float hold = h[idx];
    float hnew = (1.f - z) * n + z * hold;
    h[idx] = hnew;
    y[(size_t)b * (Ss * Hh) + t * Hh + j] = hnew;
}

__global__ void zero_kernel(float* __restrict__ p, int n)
{
    int i = blockIdx.x * blockDim.x + threadIdx.x;
    if (i < n) p[i] = 0.f;
}

// ---------------- launch ----------------
extern "C" void kernel_launch(void* const* d_in, const int* in_sizes, int n_in,
                              void* d_out, int out_size)
{
    const float* x       = (const float*)d_in[0];
    const int*   ei      = (const int*)  d_in[1];
    const float* ef      = (const float*)d_in[2];
    const float* ea      = (const float*)d_in[3];
    const float* Wx      = (const float*)d_in[4];
    const float* We      = (const float*)d_in[5];
    const float* Wf      = (const float*)d_in[6];
    const float* Wedge   = (const float*)d_in[7];
    const float* w_ih    = (const float*)d_in[8];
    const float* w_hh    = (const float*)d_in[9];
    const float* b_ih    = (const float*)d_in[10];
    const float* b_hh    = (const float*)d_in[11];
    const float* mlp_w1  = (const float*)d_in[12];
    const float* mlp_b1  = (const float*)d_in[13];
    const float* mlp_w2  = (const float*)d_in[14];
    const float* mlp_b2  = (const float*)d_in[15];
    float* out = (float*)d_out;

    float *seq, *gi, *gh, *h, *y, *z;
    cudaGetSymbolAddress((void**)&seq, g_seq);
    cudaGetSymbolAddress((void**)&gi,  g_gi);
    cudaGetSymbolAddress((void**)&gh,  g_gh);
    cudaGetSymbolAddress((void**)&h,   g_h);
    cudaGetSymbolAddress((void**)&y,   g_y);
    cudaGetSymbolAddress((void**)&z,   g_z);

    // 1) GNN -> seq [10240, 5376]
    gnn_kernel<<<Bb * Ss, 256>>>(x, ei, ef, ea, Wx, We, Wf, Wedge, seq);

    // 2) gi = seq @ w_ih^T + b_ih   [10240, 2400]  (all timesteps at once)
    {
        dim3 grid((G3H + BN - 1) / BN, (Bb * Ss + BM - 1) / BM);
        sgemm<true><<<grid, 256>>>(seq, w_ih, b_ih, gi, Bb * Ss, G3H, SEQW);
    }

    // 3) GRU recurrence
    zero_kernel<<<(Bb * Hh + 255) / 256, 256>>>(h, Bb * Hh);
    for (int t = 0; t < Ss; t++) {
        dim3 grid((G3H + BN - 1) / BN, (Bb + BM - 1) / BM);
        sgemm<true><<<grid, 256>>>(h, w_hh, b_hh, gh, Bb, G3H, Hh);
        gru_gate_kernel<<<(Bb * Hh + 255) / 256, 256>>>(gi, gh, h, y, t);
    }

    // 4) MLP
    {
        dim3 grid((MLP1 + BN - 1) / BN, (Bb + BM - 1) / BM);
        sgemm<false><<<grid, 256>>>(y, mlp_w1, mlp_b1, z, Bb, MLP1, Ss * Hh);
    }
    {
        dim3 grid((OUTW + BN - 1) / BN, (Bb + BM - 1) / BM);
        sgemm<false><<<grid, 256>>>(z, mlp_w2, mlp_b2, out, Bb, OUTW, MLP1);
    }
}

// round 2
// speedup vs baseline: 2.8126x; 2.8126x over previous
#include <cuda_runtime.h>
#include <cuda_bf16.h>
#include <math.h>
#include <limits.h>
#include <stdint.h>

// ---------------- problem constants ----------------
#define Bb   2048
#define Ss   5
#define Nn   80
#define Ee   592
#define FX   8
#define FF   4
#define FE   8
#define Dd   8
#define Hh   800
#define SEQW (Nn*Dd + Ee*Dd)   // 5376
#define G3H  (3*Hh)            // 2400
#define MLP1 1280
#define OUTW (Ss*80)           // 400

// ---------------- scratch (device globals; no allocation allowed) ----------------
__device__ __align__(128) float g_seq[(size_t)Bb*Ss*SEQW];   // [10240, 5376]
__device__ __align__(128) float g_gi [(size_t)Bb*Ss*G3H];    // [10240, 2400]
__device__ __align__(128) float g_gh [(size_t)Bb*G3H];       // [2048, 2400]
__device__ __align__(128) float g_h  [(size_t)Bb*Hh];        // [2048, 800]
__device__ __align__(128) float g_y  [(size_t)Bb*Ss*Hh];     // [2048, 4000]
__device__ __align__(128) float g_z  [(size_t)Bb*MLP1];      // [2048, 1280]
__device__ __align__(128) float g_w1t[(size_t)MLP1*(Ss*Hh)]; // [1280, 4000]
__device__ __align__(128) float g_w2t[(size_t)OUTW*MLP1];    // [400, 1280]

// ---------------- GNN: one CTA per (b,s) graph ----------------
__global__ __launch_bounds__(256)
void gnn_kernel(const float* __restrict__ x,
                const int*   __restrict__ ei,
                const float* __restrict__ ef,
                const float* __restrict__ ea,
                const float* __restrict__ Wx,
                const float* __restrict__ We,
                const float* __restrict__ Wf,
                const float* __restrict__ Wedge,
                float* __restrict__ seq)
{
    const int g = blockIdx.x;
    const float* xg  = x  + (size_t)g * Nn * FX;
    const int*   src = ei + (size_t)g * 2 * Ee;
    const int*   dst = src + Ee;
    const float* efg = ef + (size_t)g * Ee * FF;
    const float* eag = ea + (size_t)g * Ee * FE;
    float* seqg = seq + (size_t)g * SEQW;

    __shared__ float sWx[FX*Dd];
    __shared__ float sWe[FE*Dd];
    __shared__ float sWf[FF*Dd];
    __shared__ float sWedge[(2*Dd+FE)*Dd];
    __shared__ float sagg[Nn*Dd];
    __shared__ float sxo [Nn*Dd];
    __shared__ float sea [Ee*FE];
    __shared__ int   ssrc[Ee], sdst[Ee];
    __shared__ int   sminv;

    const int tid = threadIdx.x;
    if (tid == 0) sminv = INT_MAX;
    if (tid < FX*Dd)  sWx[tid] = Wx[tid];
    if (tid < FE*Dd)  sWe[tid] = We[tid];
    if (tid < FF*Dd)  sWf[tid] = Wf[tid];
    if (tid < 192)    sWedge[tid] = Wedge[tid];
    for (int i = tid; i < Nn*Dd; i += 256) sagg[i] = 0.f;
    for (int i = tid; i < Ee*FE; i += 256) sea[i] = eag[i];
    __syncthreads();

    int lm = INT_MAX;
    for (int e = tid; e < Ee; e += 256) lm = min(lm, src[e]);
    atomicMin(&sminv, lm);
    __syncthreads();
    const int minv = sminv;

    for (int e = tid; e < Ee; e += 256) {
        int s = src[e] - minv;
        int d = dst[e] - minv;
        if (d < 0) d += Nn;
        ssrc[e] = s; sdst[e] = d;
        const float* eae = &sea[e*FE];
        float fe0 = efg[e*FF+0], fe1 = efg[e*FF+1], fe2 = efg[e*FF+2], fe3 = efg[e*FF+3];
        #pragma unroll
        for (int c = 0; c < Dd; c++) {
            float m = 0.f;
            #pragma unroll
            for (int k = 0; k < FE; k++) m += eae[k] * sWe[k*Dd + c];
            m += fe0*sWf[0*Dd+c] + fe1*sWf[1*Dd+c] + fe2*sWf[2*Dd+c] + fe3*sWf[3*Dd+c];
            m = fmaxf(m, 0.f);
            atomicAdd(&sagg[d*Dd + c], m);
        }
    }
    __syncthreads();

    for (int i = tid; i < Nn*Dd; i += 256) {
        int n = i / Dd, c = i % Dd;
        float t = sagg[i];
        #pragma unroll
        for (int k = 0; k < FX; k++) t += xg[n*FX + k] * sWx[k*Dd + c];
        float v = xg[i] + fmaxf(t, 0.f);
        sxo[i] = v;
        seqg[i] = v;
    }
    __syncthreads();

    for (int e = tid; e < Ee; e += 256) {
        const float* fs = &sxo[ssrc[e]*Dd];
        const float* fd = &sxo[sdst[e]*Dd];
        const float* eae = &sea[e*FE];
        #pragma unroll
        for (int c = 0; c < Dd; c++) {
            float v = 0.f;
            #pragma unroll
            for (int k = 0; k < Dd; k++) v += fs[k]  * sWedge[(k     )*Dd + c];
            #pragma unroll
            for (int k = 0; k < Dd; k++) v += fd[k]  * sWedge[(Dd + k)*Dd + c];
            #pragma unroll
            for (int k = 0; k < FE; k++) v += eae[k] * sWedge[(2*Dd+k)*Dd + c];
            seqg[Nn*Dd + e*Dd + c] = eae[c] + fmaxf(v, 0.f);
        }
    }
}

// ---------------- TF32 tensor-core GEMM (NT): C[M,N] = A[M,K] @ B[N,K]^T + bias ----------------
// CTA tile 128x128x32, 8 warps of 64x32, mma.sync.m16n8k8 tf32.
// SMEM row stride 36 floats: fragment-load bank index = (4*gid + tig) -> conflict-free,
// and 144-byte rows keep cp.async destinations 16B-aligned.
// Requires: M % 128 == 0, K % 32 == 0 (holds for all call sites); N guarded.

#define SLD 36
#define STAGE_F (128*SLD)                  // floats per (A or B) stage
#define GEMM_SMEM_BYTES (4*STAGE_F*4)      // 2 stages x (A+B) = 73728 B

__device__ __forceinline__ uint32_t f2tf32(float x) {
    uint32_t r;
    asm("cvt.rna.tf32.f32 %0, %1;" : "=r"(r) : "f"(x));
    return r;
}

__global__ __launch_bounds__(256, 2)
void tf32_gemm_nt(const float* __restrict__ A, const float* __restrict__ B,
                  const float* __restrict__ bias, float* __restrict__ C,
                  int M, int N, int K)
{
    extern __shared__ float sm[];
    const int tid  = threadIdx.x;
    const int bm   = blockIdx.y * 128;
    const int bn   = blockIdx.x * 128;
    const int warp = tid >> 5;
    const int lane = tid & 31;
    const int gid  = lane >> 2;   // 0..7
    const int tig  = lane & 3;    // 0..3
    const int wm   = (warp >> 2) * 64;  // 0,64
    const int wn   = (warp & 3) * 32;   // 0,32,64,96

    float acc[4][4][4];
    #pragma unroll
    for (int i = 0; i < 4; i++)
        #pragma unroll
        for (int j = 0; j < 4; j++)
            #pragma unroll
            for (int v = 0; v < 4; v++) acc[i][j][v] = 0.f;

    const uint32_t s_base = (uint32_t)__cvta_generic_to_shared(sm);

    // ---- async stage loader ----
    auto load_stage = [&](int stage, int k0) {
        uint32_t a_base = s_base + (uint32_t)(stage * STAGE_F) * 4u;
        #pragma unroll
        for (int i = 0; i < 4; i++) {
            int idx = tid + i * 256;
            int m = idx >> 3, kc = idx & 7;
            const float* src = A + (size_t)(bm + m) * K + k0 + kc * 4;
            uint32_t dst = a_base + (uint32_t)(m * SLD + kc * 4) * 4u;
            asm volatile("cp.async.cg.shared.global [%0], [%1], 16;" :: "r"(dst), "l"(src));
        }
        uint32_t b_base = s_base + (uint32_t)((2 + stage) * STAGE_F) * 4u;
        #pragma unroll
        for (int i = 0; i < 4; i++) {
            int idx = tid + i * 256;
            int n = idx >> 3, kc = idx & 7;
            bool valid = (bn + n) < N;
            const float* src = valid ? (B + (size_t)(bn + n) * K + k0 + kc * 4) : B;
            uint32_t dst = b_base + (uint32_t)(n * SLD + kc * 4) * 4u;
            int sz = valid ? 16 : 0;
            asm volatile("cp.async.cg.shared.global [%0], [%1], 16, %2;" :: "r"(dst), "l"(src), "r"(sz));
        }
        asm volatile("cp.async.commit_group;");
    };

    // ---- compute one stage ----
    auto compute_stage = [&](int stage) {
        const float* as = sm + stage * STAGE_F;
        const float* bs = sm + (2 + stage) * STAGE_F;
        #pragma unroll
        for (int ks = 0; ks < 4; ks++) {
            const int kk = ks * 8 + tig;
            uint32_t af[4][4], bf[4][2];
            #pragma unroll
            for (int mi = 0; mi < 4; mi++) {
                const float* p = as + (wm + mi * 16 + gid) * SLD + kk;
                af[mi][0] = f2tf32(p[0]);
                af[mi][1] = f2tf32(p[8 * SLD]);
                af[mi][2] = f2tf32(p[4]);
                af[mi][3] = f2tf32(p[8 * SLD + 4]);
            }
            #pragma unroll
            for (int ni = 0; ni < 4; ni++) {
                const float* p = bs + (wn + ni * 8 + gid) * SLD + kk;
                bf[ni][0] = f2tf32(p[0]);
                bf[ni][1] = f2tf32(p[4]);
            }
            #pragma unroll
            for (int mi = 0; mi < 4; mi++)
                #pragma unroll
                for (int ni = 0; ni < 4; ni++) {
                    asm volatile(
                        "mma.sync.aligned.m16n8k8.row.col.f32.tf32.tf32.f32 "
                        "{%0,%1,%2,%3}, {%4,%5,%6,%7}, {%8,%9}, {%0,%1,%2,%3};"
                        : "+f"(acc[mi][ni][0]), "+f"(acc[mi][ni][1]),
                          "+f"(acc[mi][ni][2]), "+f"(acc[mi][ni][3])
                        : "r"(af[mi][0]), "r"(af[mi][1]), "r"(af[mi][2]), "r"(af[mi][3]),
                          "r"(bf[ni][0]), "r"(bf[ni][1]));
                }
        }
    };

    const int ntiles = K / 32;
    load_stage(0, 0);
    for (int kt = 0; kt < ntiles; kt++) {
        const int cur = kt & 1;
        if (kt + 1 < ntiles) {
            load_stage(cur ^ 1, (kt + 1) * 32);
            asm volatile("cp.async.wait_group 1;");
        } else {
            asm volatile("cp.async.wait_group 0;");
        }
        __syncthreads();
        compute_stage(cur);
        __syncthreads();
    }

    // ---- epilogue ----
    #pragma unroll
    for (int mi = 0; mi < 4; mi++) {
        const int r0 = bm + wm + mi * 16 + gid;
        const int r1 = r0 + 8;
        #pragma unroll
        for (int ni = 0; ni < 4; ni++) {
            const int c0 = bn + wn + ni * 8 + tig * 2;
            if (c0 < N) {   // N even, c0 even -> pair always valid when c0 < N
                const float b0 = bias[c0], b1 = bias[c0 + 1];
                float2 v0 = make_float2(acc[mi][ni][0] + b0, acc[mi][ni][1] + b1);
                float2 v1 = make_float2(acc[mi][ni][2] + b0, acc[mi][ni][3] + b1);
                *reinterpret_cast<float2*>(C + (size_t)r0 * N + c0) = v0;
                *reinterpret_cast<float2*>(C + (size_t)r1 * N + c0) = v1;
            }
        }
    }
}

// ---------------- transpose: out[C][R] = in[R][C] ----------------
__global__ __launch_bounds__(256)
void transpose_k(const float* __restrict__ in, float* __restrict__ out, int R, int C)
{
    __shared__ float t[32][33];
    const int bx = blockIdx.x * 32;  // col-block in 'in'
    const int by = blockIdx.y * 32;  // row-block in 'in'
    int x = bx + threadIdx.x;
    #pragma unroll
    for (int i = 0; i < 4; i++) {
        int y = by + threadIdx.y + i * 8;
        if (y < R && x < C) t[threadIdx.y + i * 8][threadIdx.x] = in[(size_t)y * C + x];
    }
    __syncthreads();
    x = by + threadIdx.x;            // col in 'out' = row in 'in'
    #pragma unroll
    for (int i = 0; i < 4; i++) {
        int y = bx + threadIdx.y + i * 8;  // row in 'out' = col in 'in'
        if (y < C && x < R) out[(size_t)y * R + x] = t[threadIdx.x][threadIdx.y + i * 8];
    }
}

// ---------------- GRU gates ----------------
__device__ __forceinline__ float sigmoidf(float v) { return 1.f / (1.f + expf(-v)); }

__global__ __launch_bounds__(256)
void gru_gate_kernel(const float* __restrict__ gi, const float* __restrict__ gh,
                     float* __restrict__ h, float* __restrict__ y, int t)
{
    int idx = blockIdx.x * blockDim.x + threadIdx.x;
    if (idx >= Bb * Hh) return;
    int b = idx / Hh, j = idx % Hh;
    const float* gir = gi + (size_t)(b * Ss + t) * G3H;
    const float* ghr = gh + (size_t)b * G3H;
    float ir = gir[j], iz = gir[Hh + j], in = gir[2*Hh + j];
    float hr = ghr[j], hz = ghr[Hh + j], hn = ghr[2*Hh + j];
    float r = sigmoidf(ir + hr);
    float z = sigmoidf(iz + hz);
    float n = tanhf(in + r * hn);
    float hold = h[idx];
    float hnew = (1.f - z) * n + z * hold;
    h[idx] = hnew;
    y[(size_t)b * (Ss * Hh) + t * Hh + j] = hnew;
}

__global__ void zero_kernel(float* __restrict__ p, int n)
{
    int i = blockIdx.x * blockDim.x + threadIdx.x;
    if (i < n) p[i] = 0.f;
}

// ---------------- launch ----------------
extern "C" void kernel_launch(void* const* d_in, const int* in_sizes, int n_in,
                              void* d_out, int out_size)
{
    const float* x       = (const float*)d_in[0];
    const int*   ei      = (const int*)  d_in[1];
    const float* ef      = (const float*)d_in[2];
    const float* ea      = (const float*)d_in[3];
    const float* Wx      = (const float*)d_in[4];
    const float* We      = (const float*)d_in[5];
    const float* Wf      = (const float*)d_in[6];
    const float* Wedge   = (const float*)d_in[7];
    const float* w_ih    = (const float*)d_in[8];
    const float* w_hh    = (const float*)d_in[9];
    const float* b_ih    = (const float*)d_in[10];
    const float* b_hh    = (const float*)d_in[11];
    const float* mlp_w1  = (const float*)d_in[12];
    const float* mlp_b1  = (const float*)d_in[13];
    const float* mlp_w2  = (const float*)d_in[14];
    const float* mlp_b2  = (const float*)d_in[15];
    float* out = (float*)d_out;

    float *seq, *gi, *gh, *h, *y, *z, *w1t, *w2t;
    cudaGetSymbolAddress((void**)&seq, g_seq);
    cudaGetSymbolAddress((void**)&gi,  g_gi);
    cudaGetSymbolAddress((void**)&gh,  g_gh);
    cudaGetSymbolAddress((void**)&h,   g_h);
    cudaGetSymbolAddress((void**)&y,   g_y);
    cudaGetSymbolAddress((void**)&z,   g_z);
    cudaGetSymbolAddress((void**)&w1t, g_w1t);
    cudaGetSymbolAddress((void**)&w2t, g_w2t);

    cudaFuncSetAttribute(tf32_gemm_nt,
                         cudaFuncAttributeMaxDynamicSharedMemorySize, GEMM_SMEM_BYTES);

    // 0) transpose MLP weights to NT layout
    {
        dim3 blk(32, 8);
        dim3 g1((MLP1 + 31) / 32, (Ss * Hh + 31) / 32);
        transpose_k<<<g1, blk>>>(mlp_w1, w1t, Ss * Hh, MLP1);
        dim3 g2((OUTW + 31) / 32, (MLP1 + 31) / 32);
        transpose_k<<<g2, blk>>>(mlp_w2, w2t, MLP1, OUTW);
    }

    // 1) GNN -> seq [10240, 5376]
    gnn_kernel<<<Bb * Ss, 256>>>(x, ei, ef, ea, Wx, We, Wf, Wedge, seq);

    // 2) gi = seq @ w_ih^T + b_ih   [10240, 2400]  (all timesteps at once)
    {
        dim3 grid((G3H + 127) / 128, (Bb * Ss) / 128);
        tf32_gemm_nt<<<grid, 256, GEMM_SMEM_BYTES>>>(seq, w_ih, b_ih, gi, Bb * Ss, G3H, SEQW);
    }

    // 3) GRU recurrence
    zero_kernel<<<(Bb * Hh + 255) / 256, 256>>>(h, Bb * Hh);
    for (int t = 0; t < Ss; t++) {
        dim3 grid((G3H + 127) / 128, Bb / 128);
        tf32_gemm_nt<<<grid, 256, GEMM_SMEM_BYTES>>>(h, w_hh, b_hh, gh, Bb, G3H, Hh);
        gru_gate_kernel<<<(Bb * Hh + 255) / 256, 256>>>(gi, gh, h, y, t);
    }

    // 4) MLP
    {
        dim3 grid((MLP1 + 127) / 128, Bb / 128);
        tf32_gemm_nt<<<grid, 256, GEMM_SMEM_BYTES>>>(y, w1t, mlp_b1, z, Bb, MLP1, Ss * Hh);
    }
    {
        dim3 grid((OUTW + 127) / 128, Bb / 128);
        tf32_gemm_nt<<<grid, 256, GEMM_SMEM_BYTES>>>(z, w2t, mlp_b2, out, Bb, OUTW, MLP1);
    }
}

// round 3
// speedup vs baseline: 2.8423x; 1.0105x over previous
#include <cuda_runtime.h>
#include <cuda_bf16.h>
#include <math.h>
#include <limits.h>
#include <stdint.h>

// ---------------- problem constants ----------------
#define Bb   2048
#define Ss   5
#define Nn   80
#define Ee   592
#define FX   8
#define FF   4
#define FE   8
#define Dd   8
#define Hh   800
#define SEQW (Nn*Dd + Ee*Dd)   // 5376
#define G3H  (3*Hh)            // 2400
#define MLP1 1280
#define OUTW (Ss*80)           // 400

// ---------------- scratch (device globals; no allocation allowed) ----------------
__device__ __align__(128) float g_seq [(size_t)Bb*Ss*SEQW];   // [10240, 5376] (tf32-rounded)
__device__ __align__(128) float g_gi  [(size_t)Bb*Ss*G3H];    // [10240, 2400]
__device__ __align__(128) float g_gh  [(size_t)Bb*G3H];       // [2048, 2400]
__device__ __align__(128) float g_h   [(size_t)Bb*Hh];        // [2048, 800] full precision
__device__ __align__(128) float g_hr  [(size_t)Bb*Hh];        // [2048, 800] tf32-rounded
__device__ __align__(128) float g_y   [(size_t)Bb*Ss*Hh];     // [2048, 4000] (tf32-rounded)
__device__ __align__(128) float g_z   [(size_t)Bb*MLP1];      // [2048, 1280] (tf32-rounded)
__device__ __align__(128) float g_w1t [(size_t)MLP1*(Ss*Hh)]; // [1280, 4000] (tf32-rounded)
__device__ __align__(128) float g_w2t [(size_t)OUTW*MLP1];    // [400, 1280]  (tf32-rounded)
__device__ __align__(128) float g_wihr[(size_t)G3H*SEQW];     // rounded w_ih
__device__ __align__(128) float g_whhr[(size_t)G3H*Hh];       // rounded w_hh

__device__ __forceinline__ uint32_t f2tf32(float x) {
    uint32_t r;
    asm("cvt.rna.tf32.f32 %0, %1;" : "=r"(r) : "f"(x));
    return r;
}
__device__ __forceinline__ float rtf(float x) { return __uint_as_float(f2tf32(x)); }

// ---------------- GNN: one CTA per (b,s) graph ----------------
__global__ __launch_bounds__(256)
void gnn_kernel(const float* __restrict__ x,
                const int*   __restrict__ ei,
                const float* __restrict__ ef,
                const float* __restrict__ ea,
                const float* __restrict__ Wx,
                const float* __restrict__ We,
                const float* __restrict__ Wf,
                const float* __restrict__ Wedge,
                float* __restrict__ seq)
{
    const int g = blockIdx.x;
    const float* xg  = x  + (size_t)g * Nn * FX;
    const int*   src = ei + (size_t)g * 2 * Ee;
    const int*   dst = src + Ee;
    const float* efg = ef + (size_t)g * Ee * FF;
    const float* eag = ea + (size_t)g * Ee * FE;
    float* seqg = seq + (size_t)g * SEQW;

    __shared__ float sWx[FX*Dd];
    __shared__ float sWe[FE*Dd];
    __shared__ float sWf[FF*Dd];
    __shared__ float sWedge[(2*Dd+FE)*Dd];
    __shared__ float sagg[Nn*Dd];
    __shared__ float sxo [Nn*Dd];
    __shared__ float sea [Ee*FE];
    __shared__ int   ssrc[Ee], sdst[Ee];
    __shared__ int   sminv;

    const int tid = threadIdx.x;
    if (tid == 0) sminv = INT_MAX;
    if (tid < FX*Dd)  sWx[tid] = Wx[tid];
    if (tid < FE*Dd)  sWe[tid] = We[tid];
    if (tid < FF*Dd)  sWf[tid] = Wf[tid];
    if (tid < 192)    sWedge[tid] = Wedge[tid];
    for (int i = tid; i < Nn*Dd; i += 256) sagg[i] = 0.f;
    for (int i = tid; i < Ee*FE; i += 256) sea[i] = eag[i];
    __syncthreads();

    int lm = INT_MAX;
    for (int e = tid; e < Ee; e += 256) lm = min(lm, src[e]);
    atomicMin(&sminv, lm);
    __syncthreads();
    const int minv = sminv;

    for (int e = tid; e < Ee; e += 256) {
        int s = src[e] - minv;
        int d = dst[e] - minv;
        if (d < 0) d += Nn;
        ssrc[e] = s; sdst[e] = d;
        const float* eae = &sea[e*FE];
        float fe0 = efg[e*FF+0], fe1 = efg[e*FF+1], fe2 = efg[e*FF+2], fe3 = efg[e*FF+3];
        #pragma unroll
        for (int c = 0; c < Dd; c++) {
            float m = 0.f;
            #pragma unroll
            for (int k = 0; k < FE; k++) m += eae[k] * sWe[k*Dd + c];
            m += fe0*sWf[0*Dd+c] + fe1*sWf[1*Dd+c] + fe2*sWf[2*Dd+c] + fe3*sWf[3*Dd+c];
            m = fmaxf(m, 0.f);
            atomicAdd(&sagg[d*Dd + c], m);
        }
    }
    __syncthreads();

    for (int i = tid; i < Nn*Dd; i += 256) {
        int n = i / Dd, c = i % Dd;
        float t = sagg[i];
        #pragma unroll
        for (int k = 0; k < FX; k++) t += xg[n*FX + k] * sWx[k*Dd + c];
        float v = xg[i] + fmaxf(t, 0.f);
        sxo[i] = v;
        seqg[i] = rtf(v);          // pre-rounded for TF32 GEMM
    }
    __syncthreads();

    for (int e = tid; e < Ee; e += 256) {
        const float* fs = &sxo[ssrc[e]*Dd];
        const float* fd = &sxo[sdst[e]*Dd];
        const float* eae = &sea[e*FE];
        #pragma unroll
        for (int c = 0; c < Dd; c++) {
            float v = 0.f;
            #pragma unroll
            for (int k = 0; k < Dd; k++) v += fs[k]  * sWedge[(k     )*Dd + c];
            #pragma unroll
            for (int k = 0; k < Dd; k++) v += fd[k]  * sWedge[(Dd + k)*Dd + c];
            #pragma unroll
            for (int k = 0; k < FE; k++) v += eae[k] * sWedge[(2*Dd+k)*Dd + c];
            seqg[Nn*Dd + e*Dd + c] = rtf(eae[c] + fmaxf(v, 0.f));
        }
    }
}

// ---------------- TF32 tensor-core GEMM (NT): C[M,N] = A[M,K] @ B[N,K]^T + bias ----------------
// Operands MUST be pre-rounded to TF32 bit patterns. 128x128x32 CTA tile,
// 8 warps of 64x32, mma.sync.m16n8k8, 3-stage cp.async pipeline, 1 barrier/tile.
// Requires M % 128 == 0, K % 32 == 0; N guarded.

#define SLD 36
#define ASZ (128*SLD)                      // floats per A (or B) stage
#define NSTG 3
#define GEMM_SMEM_BYTES (2*NSTG*ASZ*4)     // 110592 B

template <bool ROUND_OUT>
__global__ __launch_bounds__(256, 2)
void tf32_gemm_nt(const float* __restrict__ A, const float* __restrict__ B,
                  const float* __restrict__ bias, float* __restrict__ C,
                  int M, int N, int K)
{
    extern __shared__ float sm[];
    const int tid  = threadIdx.x;
    const int bm   = blockIdx.y * 128;
    const int bn   = blockIdx.x * 128;
    const int warp = tid >> 5;
    const int lane = tid & 31;
    const int gid  = lane >> 2;   // 0..7
    const int tig  = lane & 3;    // 0..3
    const int wm   = (warp >> 2) * 64;
    const int wn   = (warp & 3) * 32;

    float acc[4][4][4];
    #pragma unroll
    for (int i = 0; i < 4; i++)
        #pragma unroll
        for (int j = 0; j < 4; j++)
            #pragma unroll
            for (int v = 0; v < 4; v++) acc[i][j][v] = 0.f;

    const uint32_t s_base = (uint32_t)__cvta_generic_to_shared(sm);

    const int lrow = tid >> 3;           // 0..31? no: tid>>3 = 0..31 for 256 threads -> 0..31
    // each thread loads rows lrow, lrow+32, lrow+64, lrow+96 (via idx = tid + i*256)
    const int lkc  = (tid & 7) * 4;

    auto load_stage = [&](int stage, int k0) {
        uint32_t a_base = s_base + (uint32_t)(stage * ASZ) * 4u;
        const float* arow = A + (size_t)(bm + lrow) * K + k0 + lkc;
        #pragma unroll
        for (int i = 0; i < 4; i++) {
            uint32_t dst = a_base + (uint32_t)((lrow + i * 32) * SLD + lkc) * 4u;
            const float* src = arow + (size_t)(i * 32) * K;
            asm volatile("cp.async.cg.shared.global [%0], [%1], 16;" :: "r"(dst), "l"(src));
        }
        uint32_t b_base = s_base + (uint32_t)((NSTG + stage) * ASZ) * 4u;
        #pragma unroll
        for (int i = 0; i < 4; i++) {
            int n = lrow + i * 32;
            bool valid = (bn + n) < N;
            const float* src = valid ? (B + (size_t)(bn + n) * K + k0 + lkc) : B;
            uint32_t dst = b_base + (uint32_t)(n * SLD + lkc) * 4u;
            int sz = valid ? 16 : 0;
            asm volatile("cp.async.cg.shared.global [%0], [%1], 16, %2;" :: "r"(dst), "l"(src), "r"(sz));
        }
        asm volatile("cp.async.commit_group;");
    };

    auto compute_stage = [&](int stage) {
        const float* as = sm + stage * ASZ + (wm + gid) * SLD + tig;
        const float* bs = sm + (NSTG + stage) * ASZ + (wn + gid) * SLD + tig;
        #pragma unroll
        for (int ks = 0; ks < 4; ks++) {
            const int kk = ks * 8;
            uint32_t af[4][4], bf[4][2];
            #pragma unroll
            for (int mi = 0; mi < 4; mi++) {
                const float* p = as + mi * 16 * SLD + kk;
                af[mi][0] = __float_as_uint(p[0]);
                af[mi][1] = __float_as_uint(p[8 * SLD]);
                af[mi][2] = __float_as_uint(p[4]);
                af[mi][3] = __float_as_uint(p[8 * SLD + 4]);
            }
            #pragma unroll
            for (int ni = 0; ni < 4; ni++) {
                const float* p = bs + ni * 8 * SLD + kk;
                bf[ni][0] = __float_as_uint(p[0]);
                bf[ni][1] = __float_as_uint(p[4]);
            }
            #pragma unroll
            for (int mi = 0; mi < 4; mi++)
                #pragma unroll
                for (int ni = 0; ni < 4; ni++) {
                    asm volatile(
                        "mma.sync.aligned.m16n8k8.row.col.f32.tf32.tf32.f32 "
                        "{%0,%1,%2,%3}, {%4,%5,%6,%7}, {%8,%9}, {%0,%1,%2,%3};"
                        : "+f"(acc[mi][ni][0]), "+f"(acc[mi][ni][1]),
                          "+f"(acc[mi][ni][2]), "+f"(acc[mi][ni][3])
                        : "r"(af[mi][0]), "r"(af[mi][1]), "r"(af[mi][2]), "r"(af[mi][3]),
                          "r"(bf[ni][0]), "r"(bf[ni][1]));
                }
        }
    };

    const int ntiles = K / 32;           // >= 25 for all call sites
    load_stage(0, 0);
    load_stage(1, 32);

    int stage = 0;
    for (int kt = 0; kt < ntiles; kt++) {
        if (kt == ntiles - 1) { asm volatile("cp.async.wait_group 0;"); }
        else                  { asm volatile("cp.async.wait_group 1;"); }
        __syncthreads();
        if (kt + 2 < ntiles) {
            int ls = stage + 2; if (ls >= NSTG) ls -= NSTG;
            load_stage(ls, (kt + 2) * 32);
        }
        compute_stage(stage);
        if (++stage == NSTG) stage = 0;
    }

    // ---- epilogue ----
    #pragma unroll
    for (int mi = 0; mi < 4; mi++) {
        const int r0 = bm + wm + mi * 16 + gid;
        const int r1 = r0 + 8;
        #pragma unroll
        for (int ni = 0; ni < 4; ni++) {
            const int c0 = bn + wn + ni * 8 + tig * 2;
            if (c0 < N) {
                const float b0 = bias[c0], b1 = bias[c0 + 1];
                float o00 = acc[mi][ni][0] + b0, o01 = acc[mi][ni][1] + b1;
                float o10 = acc[mi][ni][2] + b0, o11 = acc[mi][ni][3] + b1;
                if (ROUND_OUT) { o00 = rtf(o00); o01 = rtf(o01); o10 = rtf(o10); o11 = rtf(o11); }
                *reinterpret_cast<float2*>(C + (size_t)r0 * N + c0) = make_float2(o00, o01);
                *reinterpret_cast<float2*>(C + (size_t)r1 * N + c0) = make_float2(o10, o11);
            }
        }
    }
}

// ---------------- transpose + tf32-round: out[C][R] = round(in[R][C]) ----------------
__global__ __launch_bounds__(256)
void transpose_k(const float* __restrict__ in, float* __restrict__ out, int R, int C)
{
    __shared__ float t[32][33];
    const int bx = blockIdx.x * 32;
    const int by = blockIdx.y * 32;
    int x = bx + threadIdx.x;
    #pragma unroll
    for (int i = 0; i < 4; i++) {
        int y = by + threadIdx.y + i * 8;
        if (y < R && x < C) t[threadIdx.y + i * 8][threadIdx.x] = in[(size_t)y * C + x];
    }
    __syncthreads();
    x = by + threadIdx.x;
    #pragma unroll
    for (int i = 0; i < 4; i++) {
        int y = bx + threadIdx.y + i * 8;
        if (y < C && x < R) out[(size_t)y * R + x] = rtf(t[threadIdx.x][threadIdx.y + i * 8]);
    }
}

// ---------------- tf32 round-copy (vectorized) ----------------
__global__ __launch_bounds__(256)
void round_copy(const float* __restrict__ in, float* __restrict__ out, int n4)
{
    int i = blockIdx.x * blockDim.x + threadIdx.x;
    if (i < n4) {
        float4 v = reinterpret_cast<const float4*>(in)[i];
        v.x = rtf(v.x); v.y = rtf(v.y); v.z = rtf(v.z); v.w = rtf(v.w);
        reinterpret_cast<float4*>(out)[i] = v;
    }
}

// ---------------- GRU gates ----------------
__device__ __forceinline__ float sigmoidf(float v) { return 1.f / (1.f + expf(-v)); }

__global__ __launch_bounds__(256)
void gru_gate_kernel(const float* __restrict__ gi, const float* __restrict__ gh,
                     float* __restrict__ h, float* __restrict__ hr,
                     float* __restrict__ y, int t)
{
    int idx = blockIdx.x * blockDim.x + threadIdx.x;
    if (idx >= Bb * Hh) return;
    int b = idx / Hh, j = idx % Hh;
    const float* gir = gi + (size_t)(b * Ss + t) * G3H;
    const float* ghr = gh + (size_t)b * G3H;
    float ir = gir[j], iz = gir[Hh + j], in = gir[2*Hh + j];
    float hrv = ghr[j], hz = ghr[Hh + j], hn = ghr[2*Hh + j];
    float r = sigmoidf(ir + hrv);
    float z = sigmoidf(iz + hz);
    float n = tanhf(in + r * hn);
    float hold = h[idx];
    float hnew = (1.f - z) * n + z * hold;
    h[idx]  = hnew;
    hr[idx] = rtf(hnew);
    y[(size_t)b * (Ss * Hh) + t * Hh + j] = rtf(hnew);
}

__global__ void zero_kernel(float* __restrict__ p, int n)
{
    int i = blockIdx.x * blockDim.x + threadIdx.x;
    if (i < n) p[i] = 0.f;
}

// ---------------- launch ----------------
extern "C" void kernel_launch(void* const* d_in, const int* in_sizes, int n_in,
                              void* d_out, int out_size)
{
    const float* x       = (const float*)d_in[0];
    const int*   ei      = (const int*)  d_in[1];
    const float* ef      = (const float*)d_in[2];
    const float* ea      = (const float*)d_in[3];
    const float* Wx      = (const float*)d_in[4];
    const float* We      = (const float*)d_in[5];
    const float* Wf      = (const float*)d_in[6];
    const float* Wedge   = (const float*)d_in[7];
    const float* w_ih    = (const float*)d_in[8];
    const float* w_hh    = (const float*)d_in[9];
    const float* b_ih    = (const float*)d_in[10];
    const float* b_hh    = (const float*)d_in[11];
    const float* mlp_w1  = (const float*)d_in[12];
    const float* mlp_b1  = (const float*)d_in[13];
    const float* mlp_w2  = (const float*)d_in[14];
    const float* mlp_b2  = (const float*)d_in[15];
    float* out = (float*)d_out;

    float *seq, *gi, *gh, *h, *hr, *y, *z, *w1t, *w2t, *wihr, *whhr;
    cudaGetSymbolAddress((void**)&seq,  g_seq);
    cudaGetSymbolAddress((void**)&gi,   g_gi);
    cudaGetSymbolAddress((void**)&gh,   g_gh);
    cudaGetSymbolAddress((void**)&h,    g_h);
    cudaGetSymbolAddress((void**)&hr,   g_hr);
    cudaGetSymbolAddress((void**)&y,    g_y);
    cudaGetSymbolAddress((void**)&z,    g_z);
    cudaGetSymbolAddress((void**)&w1t,  g_w1t);
    cudaGetSymbolAddress((void**)&w2t,  g_w2t);
    cudaGetSymbolAddress((void**)&wihr, g_wihr);
    cudaGetSymbolAddress((void**)&whhr, g_whhr);

    cudaFuncSetAttribute(tf32_gemm_nt<false>,
                         cudaFuncAttributeMaxDynamicSharedMemorySize, GEMM_SMEM_BYTES);
    cudaFuncSetAttribute(tf32_gemm_nt<true>,
                         cudaFuncAttributeMaxDynamicSharedMemorySize, GEMM_SMEM_BYTES);

    // 0) weight prep (rounded copies / transposes)
    {
        int n4 = (G3H * SEQW) / 4;
        round_copy<<<(n4 + 255) / 256, 256>>>(w_ih, wihr, n4);
        n4 = (G3H * Hh) / 4;
        round_copy<<<(n4 + 255) / 256, 256>>>(w_hh, whhr, n4);
        dim3 blk(32, 8);
        dim3 g1((MLP1 + 31) / 32, (Ss * Hh + 31) / 32);
        transpose_k<<<g1, blk>>>(mlp_w1, w1t, Ss * Hh, MLP1);
        dim3 g2((OUTW + 31) / 32, (MLP1 + 31) / 32);
        transpose_k<<<g2, blk>>>(mlp_w2, w2t, MLP1, OUTW);
    }

    // 1) GNN -> seq (pre-rounded)
    gnn_kernel<<<Bb * Ss, 256>>>(x, ei, ef, ea, Wx, We, Wf, Wedge, seq);

    // 2) gi = seq @ w_ih^T + b_ih  [10240, 2400]
    {
        dim3 grid((G3H + 127) / 128, (Bb * Ss) / 128);
        tf32_gemm_nt<false><<<grid, 256, GEMM_SMEM_BYTES>>>(seq, wihr, b_ih, gi, Bb * Ss, G3H, SEQW);
    }

    // 3) GRU recurrence
    zero_kernel<<<(Bb * Hh + 255) / 256, 256>>>(h, Bb * Hh);
    zero_kernel<<<(Bb * Hh + 255) / 256, 256>>>(hr, Bb * Hh);
    for (int t = 0; t < Ss; t++) {
        dim3 grid((G3H + 127) / 128, Bb / 128);
        tf32_gemm_nt<false><<<grid, 256, GEMM_SMEM_BYTES>>>(hr, whhr, b_hh, gh, Bb, G3H, Hh);
        gru_gate_kernel<<<(Bb * Hh + 255) / 256, 256>>>(gi, gh, h, hr, y, t);
    }

    // 4) MLP
    {
        dim3 grid((MLP1 + 127) / 128, Bb / 128);
        tf32_gemm_nt<true><<<grid, 256, GEMM_SMEM_BYTES>>>(y, w1t, mlp_b1, z, Bb, MLP1, Ss * Hh);
    }
    {
        dim3 grid((OUTW + 127) / 128, Bb / 128);
        tf32_gemm_nt<false><<<grid, 256, GEMM_SMEM_BYTES>>>(z, w2t, mlp_b2, out, Bb, OUTW, MLP1);
    }
}

// round 5
// speedup vs baseline: 2.9669x; 1.0438x over previous
#include <cuda_runtime.h>
#include <cuda_bf16.h>
#include <math.h>
#include <limits.h>
#include <stdint.h>

// ---------------- problem constants ----------------
#define Bb   2048
#define Ss   5
#define Nn   80
#define Ee   592
#define FX   8
#define FF   4
#define FE   8
#define Dd   8
#define Hh   800
#define SEQW (Nn*Dd + Ee*Dd)   // 5376
#define G3H  (3*Hh)            // 2400
#define MLP1 1280
#define OUTW (Ss*80)           // 400

// ---------------- scratch ----------------
__device__ __align__(128) float g_seq [(size_t)Bb*Ss*SEQW];
__device__ __align__(128) float g_gi  [(size_t)Bb*Ss*G3H];
__device__ __align__(128) float g_gh  [(size_t)Bb*G3H];
__device__ __align__(128) float g_h   [(size_t)Bb*Hh];
__device__ __align__(128) float g_hr  [(size_t)Bb*Hh];
__device__ __align__(128) float g_y   [(size_t)Bb*Ss*Hh];
__device__ __align__(128) float g_z   [(size_t)Bb*MLP1];
__device__ __align__(128) float g_w1t [(size_t)MLP1*(Ss*Hh)];
__device__ __align__(128) float g_w2t [(size_t)OUTW*MLP1];
__device__ __align__(128) float g_wihr[(size_t)G3H*SEQW];
__device__ __align__(128) float g_whhr[(size_t)G3H*Hh];

__device__ __forceinline__ uint32_t f2tf32(float x) {
    uint32_t r;
    asm("cvt.rna.tf32.f32 %0, %1;" : "=r"(r) : "f"(x));
    return r;
}
__device__ __forceinline__ float rtf(float x) { return __uint_as_float(f2tf32(x)); }

// ---------------- GNN: one CTA per (b,s) graph ----------------
__global__ __launch_bounds__(256)
void gnn_kernel(const float* __restrict__ x,
                const int*   __restrict__ ei,
                const float* __restrict__ ef,
                const float* __restrict__ ea,
                const float* __restrict__ Wx,
                const float* __restrict__ We,
                const float* __restrict__ Wf,
                const float* __restrict__ Wedge,
                float* __restrict__ seq)
{
    const int g = blockIdx.x;
    const float* xg  = x  + (size_t)g * Nn * FX;
    const int*   src = ei + (size_t)g * 2 * Ee;
    const int*   dst = src + Ee;
    const float* efg = ef + (size_t)g * Ee * FF;
    const float* eag = ea + (size_t)g * Ee * FE;
    float* seqg = seq + (size_t)g * SEQW;

    __shared__ float sWx[FX*Dd];
    __shared__ float sWe[FE*Dd];
    __shared__ float sWf[FF*Dd];
    __shared__ float sWedge[(2*Dd+FE)*Dd];
    __shared__ float sagg[Nn*Dd];
    __shared__ float sxo [Nn*Dd];
    __shared__ float sea [Ee*FE];
    __shared__ int   ssrc[Ee], sdst[Ee];
    __shared__ int   sminv;

    const int tid = threadIdx.x;
    if (tid == 0) sminv = INT_MAX;
    if (tid < FX*Dd)  sWx[tid] = Wx[tid];
    if (tid < FE*Dd)  sWe[tid] = We[tid];
    if (tid < FF*Dd)  sWf[tid] = Wf[tid];
    if (tid < 192)    sWedge[tid] = Wedge[tid];
    for (int i = tid; i < Nn*Dd; i += 256) sagg[i] = 0.f;
    for (int i = tid; i < Ee*FE; i += 256) sea[i] = eag[i];
    __syncthreads();

    int lm = INT_MAX;
    for (int e = tid; e < Ee; e += 256) lm = min(lm, src[e]);
    atomicMin(&sminv, lm);
    __syncthreads();
    const int minv = sminv;

    for (int e = tid; e < Ee; e += 256) {
        int s = src[e] - minv;
        int d = dst[e] - minv;
        if (d < 0) d += Nn;
        ssrc[e] = s; sdst[e] = d;
        const float* eae = &sea[e*FE];
        float fe0 = efg[e*FF+0], fe1 = efg[e*FF+1], fe2 = efg[e*FF+2], fe3 = efg[e*FF+3];
        #pragma unroll
        for (int c = 0; c < Dd; c++) {
            float m = 0.f;
            #pragma unroll
            for (int k = 0; k < FE; k++) m += eae[k] * sWe[k*Dd + c];
            m += fe0*sWf[0*Dd+c] + fe1*sWf[1*Dd+c] + fe2*sWf[2*Dd+c] + fe3*sWf[3*Dd+c];
            m = fmaxf(m, 0.f);
            atomicAdd(&sagg[d*Dd + c], m);
        }
    }
    __syncthreads();

    for (int i = tid; i < Nn*Dd; i += 256) {
        int n = i / Dd, c = i % Dd;
        float t = sagg[i];
        #pragma unroll
        for (int k = 0; k < FX; k++) t += xg[n*FX + k] * sWx[k*Dd + c];
        float v = xg[i] + fmaxf(t, 0.f);
        sxo[i] = v;
        seqg[i] = rtf(v);
    }
    __syncthreads();

    for (int e = tid; e < Ee; e += 256) {
        const float* fs = &sxo[ssrc[e]*Dd];
        const float* fd = &sxo[sdst[e]*Dd];
        const float* eae = &sea[e*FE];
        #pragma unroll
        for (int c = 0; c < Dd; c++) {
            float v = 0.f;
            #pragma unroll
            for (int k = 0; k < Dd; k++) v += fs[k]  * sWedge[(k     )*Dd + c];
            #pragma unroll
            for (int k = 0; k < Dd; k++) v += fd[k]  * sWedge[(Dd + k)*Dd + c];
            #pragma unroll
            for (int k = 0; k < FE; k++) v += eae[k] * sWedge[(2*Dd+k)*Dd + c];
            seqg[Nn*Dd + e*Dd + c] = rtf(eae[c] + fmaxf(v, 0.f));
        }
    }
}

// ---------------- TF32 tensor-core GEMM (NT): C[M,N] = A[M,K] @ B[N,K]^T + bias --------
// Operands pre-rounded to TF32. 128x128x32 CTA tile, 4 warps of 64x64
// (balances smem fragment traffic against HMMA throughput), 3-stage cp.async,
// one barrier per k-tile. Requires M % 128 == 0, K % 32 == 0; N guarded.

#define SLD 36
#define ASZ (128*SLD)
#define NSTG 3
#define GEMM_SMEM_BYTES (2*NSTG*ASZ*4)     // 110592 B

template <bool ROUND_OUT>
__global__ __launch_bounds__(128, 2)
void tf32_gemm_nt(const float* __restrict__ A, const float* __restrict__ B,
                  const float* __restrict__ bias, float* __restrict__ C,
                  int M, int N, int K)
{
    extern __shared__ float sm[];
    const int tid  = threadIdx.x;
    const int bm   = blockIdx.y * 128;
    const int bn   = blockIdx.x * 128;
    const int warp = tid >> 5;
    const int lane = tid & 31;
    const int gid  = lane >> 2;   // 0..7
    const int tig  = lane & 3;    // 0..3
    const int wm   = (warp >> 1) * 64;   // 0,64
    const int wn   = (warp & 1) * 64;    // 0,64

    float acc[4][8][4];
    #pragma unroll
    for (int i = 0; i < 4; i++)
        #pragma unroll
        for (int j = 0; j < 8; j++)
            #pragma unroll
            for (int v = 0; v < 4; v++) acc[i][j][v] = 0.f;

    const uint32_t s_base = (uint32_t)__cvta_generic_to_shared(sm);
    const int lrow = tid >> 3;           // 0..15
    const int lkc  = (tid & 7) * 4;

    auto load_stage = [&](int stage, int k0) {
        uint32_t a_base = s_base + (uint32_t)(stage * ASZ) * 4u;
        #pragma unroll
        for (int i = 0; i < 8; i++) {
            int row = lrow + i * 16;
            uint32_t dst = a_base + (uint32_t)(row * SLD + lkc) * 4u;
            const float* src = A + (size_t)(bm + row) * K + k0 + lkc;
            asm volatile("cp.async.cg.shared.global [%0], [%1], 16;" :: "r"(dst), "l"(src));
        }
        uint32_t b_base = s_base + (uint32_t)((NSTG + stage) * ASZ) * 4u;
        #pragma unroll
        for (int i = 0; i < 8; i++) {
            int n = lrow + i * 16;
            bool valid = (bn + n) < N;
            const float* src = valid ? (B + (size_t)(bn + n) * K + k0 + lkc) : B;
            uint32_t dst = b_base + (uint32_t)(n * SLD + lkc) * 4u;
            int sz = valid ? 16 : 0;
            asm volatile("cp.async.cg.shared.global [%0], [%1], 16, %2;" :: "r"(dst), "l"(src), "r"(sz));
        }
        asm volatile("cp.async.commit_group;");
    };

    auto compute_stage = [&](int stage) {
        const float* as = sm + stage * ASZ + (wm + gid) * SLD + tig;
        const float* bs = sm + (NSTG + stage) * ASZ + (wn + gid) * SLD + tig;
        #pragma unroll
        for (int ks = 0; ks < 4; ks++) {
            const int kk = ks * 8;
            uint32_t af[4][4], bf[8][2];
            #pragma unroll
            for (int mi = 0; mi < 4; mi++) {
                const float* p = as + mi * 16 * SLD + kk;
                af[mi][0] = __float_as_uint(p[0]);
                af[mi][1] = __float_as_uint(p[8 * SLD]);
                af[mi][2] = __float_as_uint(p[4]);
                af[mi][3] = __float_as_uint(p[8 * SLD + 4]);
            }
            #pragma unroll
            for (int ni = 0; ni < 8; ni++) {
                const float* p = bs + ni * 8 * SLD + kk;
                bf[ni][0] = __float_as_uint(p[0]);
                bf[ni][1] = __float_as_uint(p[4]);
            }
            #pragma unroll
            for (int mi = 0; mi < 4; mi++)
                #pragma unroll
                for (int ni = 0; ni < 8; ni++) {
                    asm volatile(
                        "mma.sync.aligned.m16n8k8.row.col.f32.tf32.tf32.f32 "
                        "{%0,%1,%2,%3}, {%4,%5,%6,%7}, {%8,%9}, {%0,%1,%2,%3};"
                        : "+f"(acc[mi][ni][0]), "+f"(acc[mi][ni][1]),
                          "+f"(acc[mi][ni][2]), "+f"(acc[mi][ni][3])
                        : "r"(af[mi][0]), "r"(af[mi][1]), "r"(af[mi][2]), "r"(af[mi][3]),
                          "r"(bf[ni][0]), "r"(bf[ni][1]));
                }
        }
    };

    const int ntiles = K / 32;
    load_stage(0, 0);
    load_stage(1, 32);

    int stage = 0;
    for (int kt = 0; kt < ntiles; kt++) {
        if (kt == ntiles - 1) { asm volatile("cp.async.wait_group 0;"); }
        else                  { asm volatile("cp.async.wait_group 1;"); }
        __syncthreads();
        if (kt + 2 < ntiles) {
            int ls = stage + 2; if (ls >= NSTG) ls -= NSTG;
            load_stage(ls, (kt + 2) * 32);
        }
        compute_stage(stage);
        if (++stage == NSTG) stage = 0;
    }

    // ---- epilogue ----
    #pragma unroll
    for (int mi = 0; mi < 4; mi++) {
        const int r0 = bm + wm + mi * 16 + gid;
        const int r1 = r0 + 8;
        #pragma unroll
        for (int ni = 0; ni < 8; ni++) {
            const int c0 = bn + wn + ni * 8 + tig * 2;
            if (c0 < N) {
                const float b0 = bias[c0], b1 = bias[c0 + 1];
                float o00 = acc[mi][ni][0] + b0, o01 = acc[mi][ni][1] + b1;
                float o10 = acc[mi][ni][2] + b0, o11 = acc[mi][ni][3] + b1;
                if (ROUND_OUT) { o00 = rtf(o00); o01 = rtf(o01); o10 = rtf(o10); o11 = rtf(o11); }
                *reinterpret_cast<float2*>(C + (size_t)r0 * N + c0) = make_float2(o00, o01);
                *reinterpret_cast<float2*>(C + (size_t)r1 * N + c0) = make_float2(o10, o11);
            }
        }
    }
}

// ---------------- transpose + tf32-round ----------------
__global__ __launch_bounds__(256)
void transpose_k(const float* __restrict__ in, float* __restrict__ out, int R, int C)
{
    __shared__ float t[32][33];
    const int bx = blockIdx.x * 32;
    const int by = blockIdx.y * 32;
    int x = bx + threadIdx.x;
    #pragma unroll
    for (int i = 0; i < 4; i++) {
        int y = by + threadIdx.y + i * 8;
        if (y < R && x < C) t[threadIdx.y + i * 8][threadIdx.x] = in[(size_t)y * C + x];
    }
    __syncthreads();
    x = by + threadIdx.x;
    #pragma unroll
    for (int i = 0; i < 4; i++) {
        int y = bx + threadIdx.y + i * 8;
        if (y < C && x < R) out[(size_t)y * R + x] = rtf(t[threadIdx.x][threadIdx.y + i * 8]);
    }
}

__global__ __launch_bounds__(256)
void round_copy(const float* __restrict__ in, float* __restrict__ out, int n4)
{
    int i = blockIdx.x * blockDim.x + threadIdx.x;
    if (i < n4) {
        float4 v = reinterpret_cast<const float4*>(in)[i];
        v.x = rtf(v.x); v.y = rtf(v.y); v.z = rtf(v.z); v.w = rtf(v.w);
        reinterpret_cast<float4*>(out)[i] = v;
    }
}

// ---------------- GRU gates ----------------
__device__ __forceinline__ float sigmoidf(float v) { return 1.f / (1.f + expf(-v)); }

__global__ __launch_bounds__(256)
void gru_gate_kernel(const float* __restrict__ gi, const float* __restrict__ gh,
                     float* __restrict__ h, float* __restrict__ hr,
                     float* __restrict__ y, int t)
{
    int idx = blockIdx.x * blockDim.x + threadIdx.x;
    if (idx >= Bb * Hh) return;
    int b = idx / Hh, j = idx % Hh;
    const float* gir = gi + (size_t)(b * Ss + t) * G3H;
    const float* ghr = gh + (size_t)b * G3H;
    float ir = gir[j], iz = gir[Hh + j], in = gir[2*Hh + j];
    float hrv = ghr[j], hz = ghr[Hh + j], hn = ghr[2*Hh + j];
    float r = sigmoidf(ir + hrv);
    float z = sigmoidf(iz + hz);
    float n = tanhf(in + r * hn);
    float hold = h[idx];
    float hnew = (1.f - z) * n + z * hold;
    h[idx]  = hnew;
    hr[idx] = rtf(hnew);
    y[(size_t)b * (Ss * Hh) + t * Hh + j] = rtf(hnew);
}

__global__ void zero_kernel(float* __restrict__ p, int n)
{
    int i = blockIdx.x * blockDim.x + threadIdx.x;
    if (i < n) p[i] = 0.f;
}

// ---------------- launch ----------------
extern "C" void kernel_launch(void* const* d_in, const int* in_sizes, int n_in,
                              void* d_out, int out_size)
{
    const float* x       = (const float*)d_in[0];
    const int*   ei      = (const int*)  d_in[1];
    const float* ef      = (const float*)d_in[2];
    const float* ea      = (const float*)d_in[3];
    const float* Wx      = (const float*)d_in[4];
    const float* We      = (const float*)d_in[5];
    const float* Wf      = (const float*)d_in[6];
    const float* Wedge   = (const float*)d_in[7];
    const float* w_ih    = (const float*)d_in[8];
    const float* w_hh    = (const float*)d_in[9];
    const float* b_ih    = (const float*)d_in[10];
    const float* b_hh    = (const float*)d_in[11];
    const float* mlp_w1  = (const float*)d_in[12];
    const float* mlp_b1  = (const float*)d_in[13];
    const float* mlp_w2  = (const float*)d_in[14];
    const float* mlp_b2  = (const float*)d_in[15];
    float* out = (float*)d_out;

    float *seq, *gi, *gh, *h, *hr, *y, *z, *w1t, *w2t, *wihr, *whhr;
    cudaGetSymbolAddress((void**)&seq,  g_seq);
    cudaGetSymbolAddress((void**)&gi,   g_gi);
    cudaGetSymbolAddress((void**)&gh,   g_gh);
    cudaGetSymbolAddress((void**)&h,    g_h);
    cudaGetSymbolAddress((void**)&hr,   g_hr);
    cudaGetSymbolAddress((void**)&y,    g_y);
    cudaGetSymbolAddress((void**)&z,    g_z);
    cudaGetSymbolAddress((void**)&w1t,  g_w1t);
    cudaGetSymbolAddress((void**)&w2t,  g_w2t);
    cudaGetSymbolAddress((void**)&wihr, g_wihr);
    cudaGetSymbolAddress((void**)&whhr, g_whhr);

    cudaFuncSetAttribute(tf32_gemm_nt<false>,
                         cudaFuncAttributeMaxDynamicSharedMemorySize, GEMM_SMEM_BYTES);
    cudaFuncSetAttribute(tf32_gemm_nt<true>,
                         cudaFuncAttributeMaxDynamicSharedMemorySize, GEMM_SMEM_BYTES);

    // 0) weight prep
    {
        int n4 = (G3H * SEQW) / 4;
        round_copy<<<(n4 + 255) / 256, 256>>>(w_ih, wihr, n4);
        n4 = (G3H * Hh) / 4;
        round_copy<<<(n4 + 255) / 256, 256>>>(w_hh, whhr, n4);
        dim3 blk(32, 8);
        dim3 g1((MLP1 + 31) / 32, (Ss * Hh + 31) / 32);
        transpose_k<<<g1, blk>>>(mlp_w1, w1t, Ss * Hh, MLP1);
        dim3 g2((OUTW + 31) / 32, (MLP1 + 31) / 32);
        transpose_k<<<g2, blk>>>(mlp_w2, w2t, MLP1, OUTW);
    }

    // 1) GNN -> seq (pre-rounded)
    gnn_kernel<<<Bb * Ss, 256>>>(x, ei, ef, ea, Wx, We, Wf, Wedge, seq);

    // 2) gi = seq @ w_ih^T + b_ih  [10240, 2400]
    {
        dim3 grid((G3H + 127) / 128, (Bb * Ss) / 128);
        tf32_gemm_nt<false><<<grid, 128, GEMM_SMEM_BYTES>>>(seq, wihr, b_ih, gi, Bb * Ss, G3H, SEQW);
    }

    // 3) GRU recurrence
    zero_kernel<<<(Bb * Hh + 255) / 256, 256>>>(h, Bb * Hh);
    zero_kernel<<<(Bb * Hh + 255) / 256, 256>>>(hr, Bb * Hh);
    for (int t = 0; t < Ss; t++) {
        dim3 grid((G3H + 127) / 128, Bb / 128);
        tf32_gemm_nt<false><<<grid, 128, GEMM_SMEM_BYTES>>>(hr, whhr, b_hh, gh, Bb, G3H, Hh);
        gru_gate_kernel<<<(Bb * Hh + 255) / 256, 256>>>(gi, gh, h, hr, y, t);
    }

    // 4) MLP
    {
        dim3 grid((MLP1 + 127) / 128, Bb / 128);
        tf32_gemm_nt<true><<<grid, 128, GEMM_SMEM_BYTES>>>(y, w1t, mlp_b1, z, Bb, MLP1, Ss * Hh);
    }
    {
        dim3 grid((OUTW + 127) / 128, Bb / 128);
        tf32_gemm_nt<false><<<grid, 128, GEMM_SMEM_BYTES>>>(z, w2t, mlp_b2, out, Bb, OUTW, MLP1);
    }
}

// round 6
// speedup vs baseline: 3.0746x; 1.0363x over previous
#include <cuda_runtime.h>
#include <cuda_bf16.h>
#include <math.h>
#include <limits.h>
#include <stdint.h>

// ---------------- problem constants ----------------
#define Bb   2048
#define Ss   5
#define Nn   80
#define Ee   592
#define FX   8
#define FF   4
#define FE   8
#define Dd   8
#define Hh   800
#define SEQW (Nn*Dd + Ee*Dd)   // 5376
#define G3H  (3*Hh)            // 2400
#define MLP1 1280
#define OUTW (Ss*80)           // 400

// ---------------- scratch ----------------
__device__ __align__(128) float g_seq [(size_t)Bb*Ss*SEQW];
__device__ __align__(128) float g_gi  [(size_t)Bb*Ss*G3H];
__device__ __align__(128) float g_gh  [(size_t)Bb*G3H];
__device__ __align__(128) float g_h   [(size_t)Bb*Hh];
__device__ __align__(128) float g_hr  [(size_t)Bb*Hh];
__device__ __align__(128) float g_y   [(size_t)Bb*Ss*Hh];
__device__ __align__(128) float g_z   [(size_t)Bb*MLP1];
__device__ __align__(128) float g_w1t [(size_t)MLP1*(Ss*Hh)];
__device__ __align__(128) float g_w2t [(size_t)OUTW*MLP1];
__device__ __align__(128) float g_wihr[(size_t)G3H*SEQW];
__device__ __align__(128) float g_whhr[(size_t)G3H*Hh];

__device__ __forceinline__ uint32_t f2tf32(float x) {
    uint32_t r;
    asm("cvt.rna.tf32.f32 %0, %1;" : "=r"(r) : "f"(x));
    return r;
}
__device__ __forceinline__ float rtf(float x) { return __uint_as_float(f2tf32(x)); }

// ---------------- GNN: one CTA per (b,s) graph ----------------
__global__ __launch_bounds__(256)
void gnn_kernel(const float* __restrict__ x,
                const int*   __restrict__ ei,
                const float* __restrict__ ef,
                const float* __restrict__ ea,
                const float* __restrict__ Wx,
                const float* __restrict__ We,
                const float* __restrict__ Wf,
                const float* __restrict__ Wedge,
                float* __restrict__ seq)
{
    const int g = blockIdx.x;
    const float* xg  = x  + (size_t)g * Nn * FX;
    const int*   src = ei + (size_t)g * 2 * Ee;
    const int*   dst = src + Ee;
    const float* efg = ef + (size_t)g * Ee * FF;
    const float* eag = ea + (size_t)g * Ee * FE;
    float* seqg = seq + (size_t)g * SEQW;

    __shared__ float sWx[FX*Dd];
    __shared__ float sWe[FE*Dd];
    __shared__ float sWf[FF*Dd];
    __shared__ float sWedge[(2*Dd+FE)*Dd];
    __shared__ float sagg[Nn*Dd];
    __shared__ float sxo [Nn*Dd];
    __shared__ float sea [Ee*FE];
    __shared__ int   ssrc[Ee], sdst[Ee];
    __shared__ int   sminv;

    const int tid = threadIdx.x;
    if (tid == 0) sminv = INT_MAX;
    if (tid < FX*Dd)  sWx[tid] = Wx[tid];
    if (tid < FE*Dd)  sWe[tid] = We[tid];
    if (tid < FF*Dd)  sWf[tid] = Wf[tid];
    if (tid < 192)    sWedge[tid] = Wedge[tid];
    for (int i = tid; i < Nn*Dd; i += 256) sagg[i] = 0.f;
    for (int i = tid; i < Ee*FE; i += 256) sea[i] = eag[i];
    __syncthreads();

    int lm = INT_MAX;
    for (int e = tid; e < Ee; e += 256) lm = min(lm, src[e]);
    atomicMin(&sminv, lm);
    __syncthreads();
    const int minv = sminv;

    for (int e = tid; e < Ee; e += 256) {
        int s = src[e] - minv;
        int d = dst[e] - minv;
        if (d < 0) d += Nn;
        ssrc[e] = s; sdst[e] = d;
        const float* eae = &sea[e*FE];
        float fe0 = efg[e*FF+0], fe1 = efg[e*FF+1], fe2 = efg[e*FF+2], fe3 = efg[e*FF+3];
        #pragma unroll
        for (int c = 0; c < Dd; c++) {
            float m = 0.f;
            #pragma unroll
            for (int k = 0; k < FE; k++) m += eae[k] * sWe[k*Dd + c];
            m += fe0*sWf[0*Dd+c] + fe1*sWf[1*Dd+c] + fe2*sWf[2*Dd+c] + fe3*sWf[3*Dd+c];
            m = fmaxf(m, 0.f);
            atomicAdd(&sagg[d*Dd + c], m);
        }
    }
    __syncthreads();

    for (int i = tid; i < Nn*Dd; i += 256) {
        int n = i / Dd, c = i % Dd;
        float t = sagg[i];
        #pragma unroll
        for (int k = 0; k < FX; k++) t += xg[n*FX + k] * sWx[k*Dd + c];
        float v = xg[i] + fmaxf(t, 0.f);
        sxo[i] = v;
        seqg[i] = rtf(v);
    }
    __syncthreads();

    for (int e = tid; e < Ee; e += 256) {
        const float* fs = &sxo[ssrc[e]*Dd];
        const float* fd = &sxo[sdst[e]*Dd];
        const float* eae = &sea[e*FE];
        #pragma unroll
        for (int c = 0; c < Dd; c++) {
            float v = 0.f;
            #pragma unroll
            for (int k = 0; k < Dd; k++) v += fs[k]  * sWedge[(k     )*Dd + c];
            #pragma unroll
            for (int k = 0; k < Dd; k++) v += fd[k]  * sWedge[(Dd + k)*Dd + c];
            #pragma unroll
            for (int k = 0; k < FE; k++) v += eae[k] * sWedge[(2*Dd+k)*Dd + c];
            seqg[Nn*Dd + e*Dd + c] = rtf(eae[c] + fmaxf(v, 0.f));
        }
    }
}

// ---------------- TF32 tensor-core GEMM (NT): C[M,N] = A[M,K] @ B[N,K]^T + bias --------
// Operands pre-rounded to TF32. 128x128x32 CTA tile, 4 warps of 64x64,
// ldmatrix (LDSM.x4) fragment loads, 3-stage cp.async, one barrier per k-tile.
// Requires M % 128 == 0, K % 32 == 0; N guarded.

#define SLD 36
#define ASZ (128*SLD)
#define NSTG 3
#define GEMM_SMEM_BYTES (2*NSTG*ASZ*4)     // 110592 B

template <bool ROUND_OUT>
__global__ __launch_bounds__(128, 2)
void tf32_gemm_nt(const float* __restrict__ A, const float* __restrict__ B,
                  const float* __restrict__ bias, float* __restrict__ C,
                  int M, int N, int K)
{
    extern __shared__ float sm[];
    const int tid  = threadIdx.x;
    const int bm   = blockIdx.y * 128;
    const int bn   = blockIdx.x * 128;
    const int warp = tid >> 5;
    const int lane = tid & 31;
    const int gid  = lane >> 2;   // 0..7
    const int tig  = lane & 3;    // 0..3
    const int wm   = (warp >> 1) * 64;   // 0,64
    const int wn   = (warp & 1) * 64;    // 0,64

    float acc[4][8][4];
    #pragma unroll
    for (int i = 0; i < 4; i++)
        #pragma unroll
        for (int j = 0; j < 8; j++)
            #pragma unroll
            for (int v = 0; v < 4; v++) acc[i][j][v] = 0.f;

    const uint32_t s_base = (uint32_t)__cvta_generic_to_shared(sm);
    const int lrow = tid >> 3;           // 0..15
    const int lkc  = (tid & 7) * 4;

    // ldmatrix per-lane source rows:
    // A x4 covers 16 m-rows x 8 k:  m0:(rows 0-7,k 0-3) m1:(rows 8-15,k 0-3)
    //                               m2:(rows 0-7,k 4-7) m3:(rows 8-15,k 4-7)
    //   -> af[0..3] = (gid,tig),(gid+8,tig),(gid,tig+4),(gid+8,tig+4)   [mma order]
    // B x4 covers 16 n-rows x 8 k:  m0:(n 0-7,k 0-3) m1:(n 0-7,k 4-7)
    //                               m2:(n 8-15,k 0-3) m3:(n 8-15,k 4-7)
    //   -> r0,r1 = b-frag of ni even; r2,r3 = b-frag of ni odd
    const int sel = lane >> 3;           // 0..3
    const int wth = lane & 7;
    const int a_row = wm + (sel & 1) * 8 + wth;
    const int a_k   = (sel >> 1) * 4;
    const int b_row = wn + (sel >> 1) * 8 + wth;
    const int b_k   = (sel & 1) * 4;

    auto load_stage = [&](int stage, int k0) {
        uint32_t a_base = s_base + (uint32_t)(stage * ASZ) * 4u;
        #pragma unroll
        for (int i = 0; i < 8; i++) {
            int row = lrow + i * 16;
            uint32_t dst = a_base + (uint32_t)(row * SLD + lkc) * 4u;
            const float* src = A + (size_t)(bm + row) * K + k0 + lkc;
            asm volatile("cp.async.cg.shared.global [%0], [%1], 16;" :: "r"(dst), "l"(src));
        }
        uint32_t b_base = s_base + (uint32_t)((NSTG + stage) * ASZ) * 4u;
        #pragma unroll
        for (int i = 0; i < 8; i++) {
            int n = lrow + i * 16;
            bool valid = (bn + n) < N;
            const float* src = valid ? (B + (size_t)(bn + n) * K + k0 + lkc) : B;
            uint32_t dst = b_base + (uint32_t)(n * SLD + lkc) * 4u;
            int sz = valid ? 16 : 0;
            asm volatile("cp.async.cg.shared.global [%0], [%1], 16, %2;" :: "r"(dst), "l"(src), "r"(sz));
        }
        asm volatile("cp.async.commit_group;");
    };

    auto compute_stage = [&](int stage) {
        const uint32_t abase = s_base + (uint32_t)(stage * ASZ + a_row * SLD + a_k) * 4u;
        const uint32_t bbase = s_base + (uint32_t)((NSTG + stage) * ASZ + b_row * SLD + b_k) * 4u;
        #pragma unroll
        for (int ks = 0; ks < 4; ks++) {
            uint32_t af[4][4], bf[8][2];
            #pragma unroll
            for (int mi = 0; mi < 4; mi++) {
                uint32_t sa = abase + (uint32_t)(mi * 16 * SLD + ks * 8) * 4u;
                asm volatile(
                    "ldmatrix.sync.aligned.m8n8.x4.shared.b16 {%0,%1,%2,%3}, [%4];"
                    : "=r"(af[mi][0]), "=r"(af[mi][1]), "=r"(af[mi][2]), "=r"(af[mi][3])
                    : "r"(sa));
            }
            #pragma unroll
            for (int nn = 0; nn < 4; nn++) {
                uint32_t sb = bbase + (uint32_t)(nn * 16 * SLD + ks * 8) * 4u;
                asm volatile(
                    "ldmatrix.sync.aligned.m8n8.x4.shared.b16 {%0,%1,%2,%3}, [%4];"
                    : "=r"(bf[2*nn][0]), "=r"(bf[2*nn][1]),
                      "=r"(bf[2*nn+1][0]), "=r"(bf[2*nn+1][1])
                    : "r"(sb));
            }
            #pragma unroll
            for (int mi = 0; mi < 4; mi++)
                #pragma unroll
                for (int ni = 0; ni < 8; ni++) {
                    asm volatile(
                        "mma.sync.aligned.m16n8k8.row.col.f32.tf32.tf32.f32 "
                        "{%0,%1,%2,%3}, {%4,%5,%6,%7}, {%8,%9}, {%0,%1,%2,%3};"
                        : "+f"(acc[mi][ni][0]), "+f"(acc[mi][ni][1]),
                          "+f"(acc[mi][ni][2]), "+f"(acc[mi][ni][3])
                        : "r"(af[mi][0]), "r"(af[mi][1]), "r"(af[mi][2]), "r"(af[mi][3]),
                          "r"(bf[ni][0]), "r"(bf[ni][1]));
                }
        }
    };

    const int ntiles = K / 32;
    load_stage(0, 0);
    load_stage(1, 32);

    int stage = 0;
    for (int kt = 0; kt < ntiles; kt++) {
        if (kt == ntiles - 1) { asm volatile("cp.async.wait_group 0;"); }
        else                  { asm volatile("cp.async.wait_group 1;"); }
        __syncthreads();
        if (kt + 2 < ntiles) {
            int ls = stage + 2; if (ls >= NSTG) ls -= NSTG;
            load_stage(ls, (kt + 2) * 32);
        }
        compute_stage(stage);
        if (++stage == NSTG) stage = 0;
    }

    // ---- epilogue ----
    #pragma unroll
    for (int mi = 0; mi < 4; mi++) {
        const int r0 = bm + wm + mi * 16 + gid;
        const int r1 = r0 + 8;
        #pragma unroll
        for (int ni = 0; ni < 8; ni++) {
            const int c0 = bn + wn + ni * 8 + tig * 2;
            if (c0 < N) {
                const float b0 = bias[c0], b1 = bias[c0 + 1];
                float o00 = acc[mi][ni][0] + b0, o01 = acc[mi][ni][1] + b1;
                float o10 = acc[mi][ni][2] + b0, o11 = acc[mi][ni][3] + b1;
                if (ROUND_OUT) { o00 = rtf(o00); o01 = rtf(o01); o10 = rtf(o10); o11 = rtf(o11); }
                *reinterpret_cast<float2*>(C + (size_t)r0 * N + c0) = make_float2(o00, o01);
                *reinterpret_cast<float2*>(C + (size_t)r1 * N + c0) = make_float2(o10, o11);
            }
        }
    }
}

// ---------------- transpose + tf32-round ----------------
__global__ __launch_bounds__(256)
void transpose_k(const float* __restrict__ in, float* __restrict__ out, int R, int C)
{
    __shared__ float t[32][33];
    const int bx = blockIdx.x * 32;
    const int by = blockIdx.y * 32;
    int x = bx + threadIdx.x;
    #pragma unroll
    for (int i = 0; i < 4; i++) {
        int y = by + threadIdx.y + i * 8;
        if (y < R && x < C) t[threadIdx.y + i * 8][threadIdx.x] = in[(size_t)y * C + x];
    }
    __syncthreads();
    x = by + threadIdx.x;
    #pragma unroll
    for (int i = 0; i < 4; i++) {
        int y = bx + threadIdx.y + i * 8;
        if (y < C && x < R) out[(size_t)y * R + x] = rtf(t[threadIdx.x][threadIdx.y + i * 8]);
    }
}

__global__ __launch_bounds__(256)
void round_copy(const float* __restrict__ in, float* __restrict__ out, int n4)
{
    int i = blockIdx.x * blockDim.x + threadIdx.x;
    if (i < n4) {
        float4 v = reinterpret_cast<const float4*>(in)[i];
        v.x = rtf(v.x); v.y = rtf(v.y); v.z = rtf(v.z); v.w = rtf(v.w);
        reinterpret_cast<float4*>(out)[i] = v;
    }
}

// ---------------- GRU gates ----------------
__device__ __forceinline__ float sigmoidf(float v) { return 1.f / (1.f + expf(-v)); }

__global__ __launch_bounds__(256)
void gru_gate_kernel(const float* __restrict__ gi, const float* __restrict__ gh,
                     float* __restrict__ h, float* __restrict__ hr,
                     float* __restrict__ y, int t)
{
    int idx = blockIdx.x * blockDim.x + threadIdx.x;
    if (idx >= Bb * Hh) return;
    int b = idx / Hh, j = idx % Hh;
    const float* gir = gi + (size_t)(b * Ss + t) * G3H;
    const float* ghr = gh + (size_t)b * G3H;
    float ir = gir[j], iz = gir[Hh + j], in = gir[2*Hh + j];
    float hrv = ghr[j], hz = ghr[Hh + j], hn = ghr[2*Hh + j];
    float r = sigmoidf(ir + hrv);
    float z = sigmoidf(iz + hz);
    float n = tanhf(in + r * hn);
    float hold = h[idx];
    float hnew = (1.f - z) * n + z * hold;
    h[idx]  = hnew;
    hr[idx] = rtf(hnew);
    y[(size_t)b * (Ss * Hh) + t * Hh + j] = rtf(hnew);
}

__global__ void zero_kernel(float* __restrict__ p, int n)
{
    int i = blockIdx.x * blockDim.x + threadIdx.x;
    if (i < n) p[i] = 0.f;
}

// ---------------- launch ----------------
extern "C" void kernel_launch(void* const* d_in, const int* in_sizes, int n_in,
                              void* d_out, int out_size)
{
    const float* x       = (const float*)d_in[0];
    const int*   ei      = (const int*)  d_in[1];
    const float* ef      = (const float*)d_in[2];
    const float* ea      = (const float*)d_in[3];
    const float* Wx      = (const float*)d_in[4];
    const float* We      = (const float*)d_in[5];
    const float* Wf      = (const float*)d_in[6];
    const float* Wedge   = (const float*)d_in[7];
    const float* w_ih    = (const float*)d_in[8];
    const float* w_hh    = (const float*)d_in[9];
    const float* b_ih    = (const float*)d_in[10];
    const float* b_hh    = (const float*)d_in[11];
    const float* mlp_w1  = (const float*)d_in[12];
    const float* mlp_b1  = (const float*)d_in[13];
    const float* mlp_w2  = (const float*)d_in[14];
    const float* mlp_b2  = (const float*)d_in[15];
    float* out = (float*)d_out;

    float *seq, *gi, *gh, *h, *hr, *y, *z, *w1t, *w2t, *wihr, *whhr;
    cudaGetSymbolAddress((void**)&seq,  g_seq);
    cudaGetSymbolAddress((void**)&gi,   g_gi);
    cudaGetSymbolAddress((void**)&gh,   g_gh);
    cudaGetSymbolAddress((void**)&h,    g_h);
    cudaGetSymbolAddress((void**)&hr,   g_hr);
    cudaGetSymbolAddress((void**)&y,    g_y);
    cudaGetSymbolAddress((void**)&z,    g_z);
    cudaGetSymbolAddress((void**)&w1t,  g_w1t);
    cudaGetSymbolAddress((void**)&w2t,  g_w2t);
    cudaGetSymbolAddress((void**)&wihr, g_wihr);
    cudaGetSymbolAddress((void**)&whhr, g_whhr);

    cudaFuncSetAttribute(tf32_gemm_nt<false>,
                         cudaFuncAttributeMaxDynamicSharedMemorySize, GEMM_SMEM_BYTES);
    cudaFuncSetAttribute(tf32_gemm_nt<true>,
                         cudaFuncAttributeMaxDynamicSharedMemorySize, GEMM_SMEM_BYTES);

    // 0) weight prep
    {
        int n4 = (G3H * SEQW) / 4;
        round_copy<<<(n4 + 255) / 256, 256>>>(w_ih, wihr, n4);
        n4 = (G3H * Hh) / 4;
        round_copy<<<(n4 + 255) / 256, 256>>>(w_hh, whhr, n4);
        dim3 blk(32, 8);
        dim3 g1((MLP1 + 31) / 32, (Ss * Hh + 31) / 32);
        transpose_k<<<g1, blk>>>(mlp_w1, w1t, Ss * Hh, MLP1);
        dim3 g2((OUTW + 31) / 32, (MLP1 + 31) / 32);
        transpose_k<<<g2, blk>>>(mlp_w2, w2t, MLP1, OUTW);
    }

    // 1) GNN -> seq (pre-rounded)
    gnn_kernel<<<Bb * Ss, 256>>>(x, ei, ef, ea, Wx, We, Wf, Wedge, seq);

    // 2) gi = seq @ w_ih^T + b_ih  [10240, 2400]
    {
        dim3 grid((G3H + 127) / 128, (Bb * Ss) / 128);
        tf32_gemm_nt<false><<<grid, 128, GEMM_SMEM_BYTES>>>(seq, wihr, b_ih, gi, Bb * Ss, G3H, SEQW);
    }

    // 3) GRU recurrence
    zero_kernel<<<(Bb * Hh + 255) / 256, 256>>>(h, Bb * Hh);
    zero_kernel<<<(Bb * Hh + 255) / 256, 256>>>(hr, Bb * Hh);
    for (int t = 0; t < Ss; t++) {
        dim3 grid((G3H + 127) / 128, Bb / 128);
        tf32_gemm_nt<false><<<grid, 128, GEMM_SMEM_BYTES>>>(hr, whhr, b_hh, gh, Bb, G3H, Hh);
        gru_gate_kernel<<<(Bb * Hh + 255) / 256, 256>>>(gi, gh, h, hr, y, t);
    }

    // 4) MLP
    {
        dim3 grid((MLP1 + 127) / 128, Bb / 128);
        tf32_gemm_nt<true><<<grid, 128, GEMM_SMEM_BYTES>>>(y, w1t, mlp_b1, z, Bb, MLP1, Ss * Hh);
    }
    {
        dim3 grid((OUTW + 127) / 128, Bb / 128);
        tf32_gemm_nt<false><<<grid, 128, GEMM_SMEM_BYTES>>>(z, w2t, mlp_b2, out, Bb, OUTW, MLP1);
    }
}

// round 7
// speedup vs baseline: 4.1460x; 1.3484x over previous
#include <cuda_runtime.h>
#include <cuda_fp16.h>
#include <math.h>
#include <limits.h>
#include <stdint.h>

// ---------------- problem constants ----------------
#define Bb   2048
#define Ss   5
#define Nn   80
#define Ee   592
#define FX   8
#define FF   4
#define FE   8
#define Dd   8
#define Hh   800
#define SEQW (Nn*Dd + Ee*Dd)   // 5376
#define G3H  (3*Hh)            // 2400
#define MLP1 1280
#define OUTW (Ss*80)           // 400
#define HPAD 832               // 800 -> x64
#define YPAD 4032              // 4000 -> x64

// ---------------- scratch (device globals, zero-initialized; padding never written) ----
__device__ __align__(128) __half g_seq [(size_t)Bb*Ss*SEQW];
__device__ __align__(128) __half g_wih [(size_t)G3H*SEQW];
__device__ __align__(128) __half g_whh [(size_t)G3H*HPAD];
__device__ __align__(128) __half g_w1t [(size_t)MLP1*YPAD];
__device__ __align__(128) __half g_w2t [(size_t)OUTW*MLP1];
__device__ __align__(128) __half g_hr  [(size_t)Bb*HPAD];
__device__ __align__(128) __half g_y   [(size_t)Bb*YPAD];
__device__ __align__(128) __half g_z   [(size_t)Bb*MLP1];
__device__ __align__(128) float  g_gi  [(size_t)Bb*Ss*G3H];
__device__ __align__(128) float  g_gh  [(size_t)Bb*G3H];
__device__ __align__(128) float  g_h   [(size_t)Bb*Hh];

// ---------------- GNN: one CTA per (b,s) graph; writes half seq ----------------
__global__ __launch_bounds__(256)
void gnn_kernel(const float* __restrict__ x,
                const int*   __restrict__ ei,
                const float* __restrict__ ef,
                const float* __restrict__ ea,
                const float* __restrict__ Wx,
                const float* __restrict__ We,
                const float* __restrict__ Wf,
                const float* __restrict__ Wedge,
                __half* __restrict__ seq)
{
    const int g = blockIdx.x;
    const float* xg  = x  + (size_t)g * Nn * FX;
    const int*   src = ei + (size_t)g * 2 * Ee;
    const int*   dst = src + Ee;
    const float* efg = ef + (size_t)g * Ee * FF;
    const float* eag = ea + (size_t)g * Ee * FE;
    __half* seqg = seq + (size_t)g * SEQW;

    __shared__ float sWx[FX*Dd];
    __shared__ float sWe[FE*Dd];
    __shared__ float sWf[FF*Dd];
    __shared__ float sWedge[(2*Dd+FE)*Dd];
    __shared__ float sagg[Nn*Dd];
    __shared__ float sxo [Nn*Dd];
    __shared__ float sea [Ee*FE];
    __shared__ int   ssrc[Ee], sdst[Ee];
    __shared__ int   sminv;

    const int tid = threadIdx.x;
    if (tid == 0) sminv = INT_MAX;
    if (tid < FX*Dd)  sWx[tid] = Wx[tid];
    if (tid < FE*Dd)  sWe[tid] = We[tid];
    if (tid < FF*Dd)  sWf[tid] = Wf[tid];
    if (tid < 192)    sWedge[tid] = Wedge[tid];
    for (int i = tid; i < Nn*Dd; i += 256) sagg[i] = 0.f;
    for (int i = tid; i < Ee*FE; i += 256) sea[i] = eag[i];
    __syncthreads();

    int lm = INT_MAX;
    for (int e = tid; e < Ee; e += 256) lm = min(lm, src[e]);
    atomicMin(&sminv, lm);
    __syncthreads();
    const int minv = sminv;

    for (int e = tid; e < Ee; e += 256) {
        int s = src[e] - minv;
        int d = dst[e] - minv;
        if (d < 0) d += Nn;
        ssrc[e] = s; sdst[e] = d;
        const float* eae = &sea[e*FE];
        float fe0 = efg[e*FF+0], fe1 = efg[e*FF+1], fe2 = efg[e*FF+2], fe3 = efg[e*FF+3];
        #pragma unroll
        for (int c = 0; c < Dd; c++) {
            float m = 0.f;
            #pragma unroll
            for (int k = 0; k < FE; k++) m += eae[k] * sWe[k*Dd + c];
            m += fe0*sWf[0*Dd+c] + fe1*sWf[1*Dd+c] + fe2*sWf[2*Dd+c] + fe3*sWf[3*Dd+c];
            m = fmaxf(m, 0.f);
            atomicAdd(&sagg[d*Dd + c], m);
        }
    }
    __syncthreads();

    for (int i = tid; i < Nn*Dd; i += 256) {
        int n = i / Dd, c = i % Dd;
        float t = sagg[i];
        #pragma unroll
        for (int k = 0; k < FX; k++) t += xg[n*FX + k] * sWx[k*Dd + c];
        float v = xg[i] + fmaxf(t, 0.f);
        sxo[i] = v;
        seqg[i] = __float2half_rn(v);
    }
    __syncthreads();

    for (int e = tid; e < Ee; e += 256) {
        const float* fs = &sxo[ssrc[e]*Dd];
        const float* fd = &sxo[sdst[e]*Dd];
        const float* eae = &sea[e*FE];
        #pragma unroll
        for (int c = 0; c < Dd; c++) {
            float v = 0.f;
            #pragma unroll
            for (int k = 0; k < Dd; k++) v += fs[k]  * sWedge[(k     )*Dd + c];
            #pragma unroll
            for (int k = 0; k < Dd; k++) v += fd[k]  * sWedge[(Dd + k)*Dd + c];
            #pragma unroll
            for (int k = 0; k < FE; k++) v += eae[k] * sWedge[(2*Dd+k)*Dd + c];
            seqg[Nn*Dd + e*Dd + c] = __float2half_rn(eae[c] + fmaxf(v, 0.f));
        }
    }
}

// ---------------- FP16 tensor-core GEMM (NT): C[M,N] = A[M,K] @ B[N,K]^T + bias -----
// mma.m16n8k16.f16 with fp32 accumulation (fp16 mantissa == tf32 mantissa).
// 128x128 CTA tile, K-tile 64 halfs, 4 warps of 64x64, ldmatrix x4 fragments,
// 3-stage cp.async, one barrier per k-tile. Rows padded to 72 halfs (144B):
// 16*r mod 128 distinct -> conflict-free for cp.async stores and ldmatrix.
// Requires M % 128 == 0, K % 64 == 0; N guarded.

#define SLDH 72
#define ASZB (128*SLDH*2)                  // 18432 B per operand stage
#define NSTG 3
#define GEMM_SMEM_BYTES (2*NSTG*ASZB)      // 110592 B

template <int OUTM>   // 0: float out, 1: half out
__global__ __launch_bounds__(128, 2)
void h16_gemm_nt(const __half* __restrict__ A, const __half* __restrict__ B,
                 const float* __restrict__ bias,
                 float* __restrict__ Cf, __half* __restrict__ Ch,
                 int M, int N, int K)
{
    extern __shared__ char smc[];
    const int tid  = threadIdx.x;
    const int bm   = blockIdx.y * 128;
    const int bn   = blockIdx.x * 128;
    const int warp = tid >> 5;
    const int lane = tid & 31;
    const int gid  = lane >> 2;
    const int tig  = lane & 3;
    const int wm   = (warp >> 1) * 64;
    const int wn   = (warp & 1) * 64;

    float acc[4][8][4];
    #pragma unroll
    for (int i = 0; i < 4; i++)
        #pragma unroll
        for (int j = 0; j < 8; j++)
            #pragma unroll
            for (int v = 0; v < 4; v++) acc[i][j][v] = 0.f;

    const uint32_t s_base = (uint32_t)__cvta_generic_to_shared(smc);
    const int lrow = tid >> 3;          // 0..15
    const int lch  = (tid & 7) * 8;     // half offset of 16B chunk

    // ldmatrix lane->row mapping (m8n8.x4.b16)
    const int sel = lane >> 3;          // 0..3
    const int wth = lane & 7;
    const int a_row = (sel & 1) * 8 + wth;   // matrices: (m0-7,k0-7),(m8-15,k0-7),(m0-7,k8-15),(m8-15,k8-15)
    const int a_k   = (sel >> 1) * 8;
    const int b_row = (sel >> 1) * 8 + wth;  // matrices: (n0-7,k0-7),(n0-7,k8-15),(n8-15,k0-7),(n8-15,k8-15)
    const int b_k   = (sel & 1) * 8;

    auto load_stage = [&](int stage, int k0) {
        uint32_t a_base = s_base + (uint32_t)(stage * ASZB);
        #pragma unroll
        for (int i = 0; i < 8; i++) {
            int row = lrow + i * 16;
            uint32_t dst = a_base + (uint32_t)(row * SLDH + lch) * 2u;
            const __half* src = A + (size_t)(bm + row) * K + k0 + lch;
            asm volatile("cp.async.cg.shared.global [%0], [%1], 16;" :: "r"(dst), "l"(src));
        }
        uint32_t b_base = s_base + (uint32_t)((NSTG + stage) * ASZB);
        #pragma unroll
        for (int i = 0; i < 8; i++) {
            int n = lrow + i * 16;
            bool valid = (bn + n) < N;
            const __half* src = valid ? (B + (size_t)(bn + n) * K + k0 + lch) : B;
            uint32_t dst = b_base + (uint32_t)(n * SLDH + lch) * 2u;
            int sz = valid ? 16 : 0;
            asm volatile("cp.async.cg.shared.global [%0], [%1], 16, %2;" :: "r"(dst), "l"(src), "r"(sz));
        }
        asm volatile("cp.async.commit_group;");
    };

    auto compute_stage = [&](int stage) {
        const uint32_t abase = s_base + (uint32_t)(stage * ASZB)
                             + (uint32_t)((wm + a_row) * SLDH + a_k) * 2u;
        const uint32_t bbase = s_base + (uint32_t)((NSTG + stage) * ASZB)
                             + (uint32_t)((wn + b_row) * SLDH + b_k) * 2u;
        #pragma unroll
        for (int ks = 0; ks < 4; ks++) {           // 4 x k16 = 64
            uint32_t af[4][4], bf[8][2];
            #pragma unroll
            for (int mi = 0; mi < 4; mi++) {
                uint32_t sa = abase + (uint32_t)(mi * 16 * SLDH + ks * 16) * 2u;
                asm volatile(
                    "ldmatrix.sync.aligned.m8n8.x4.shared.b16 {%0,%1,%2,%3}, [%4];"
                    : "=r"(af[mi][0]), "=r"(af[mi][1]), "=r"(af[mi][2]), "=r"(af[mi][3])
                    : "r"(sa));
            }
            #pragma unroll
            for (int nn = 0; nn < 4; nn++) {
                uint32_t sb = bbase + (uint32_t)(nn * 16 * SLDH + ks * 16) * 2u;
                asm volatile(
                    "ldmatrix.sync.aligned.m8n8.x4.shared.b16 {%0,%1,%2,%3}, [%4];"
                    : "=r"(bf[2*nn][0]), "=r"(bf[2*nn][1]),
                      "=r"(bf[2*nn+1][0]), "=r"(bf[2*nn+1][1])
                    : "r"(sb));
            }
            #pragma unroll
            for (int mi = 0; mi < 4; mi++)
                #pragma unroll
                for (int ni = 0; ni < 8; ni++) {
                    asm volatile(
                        "mma.sync.aligned.m16n8k16.row.col.f32.f16.f16.f32 "
                        "{%0,%1,%2,%3}, {%4,%5,%6,%7}, {%8,%9}, {%0,%1,%2,%3};"
                        : "+f"(acc[mi][ni][0]), "+f"(acc[mi][ni][1]),
                          "+f"(acc[mi][ni][2]), "+f"(acc[mi][ni][3])
                        : "r"(af[mi][0]), "r"(af[mi][1]), "r"(af[mi][2]), "r"(af[mi][3]),
                          "r"(bf[ni][0]), "r"(bf[ni][1]));
                }
        }
    };

    const int ntiles = K / 64;
    load_stage(0, 0);
    load_stage(1, 64);

    int stage = 0;
    for (int kt = 0; kt < ntiles; kt++) {
        if (kt == ntiles - 1) { asm volatile("cp.async.wait_group 0;"); }
        else                  { asm volatile("cp.async.wait_group 1;"); }
        __syncthreads();
        if (kt + 2 < ntiles) {
            int ls = stage + 2; if (ls >= NSTG) ls -= NSTG;
            load_stage(ls, (kt + 2) * 64);
        }
        compute_stage(stage);
        if (++stage == NSTG) stage = 0;
    }

    // ---- epilogue ----
    #pragma unroll
    for (int mi = 0; mi < 4; mi++) {
        const int r0 = bm + wm + mi * 16 + gid;
        const int r1 = r0 + 8;
        #pragma unroll
        for (int ni = 0; ni < 8; ni++) {
            const int c0 = bn + wn + ni * 8 + tig * 2;
            if (c0 < N) {
                const float b0 = bias[c0], b1 = bias[c0 + 1];
                float o00 = acc[mi][ni][0] + b0, o01 = acc[mi][ni][1] + b1;
                float o10 = acc[mi][ni][2] + b0, o11 = acc[mi][ni][3] + b1;
                if (OUTM == 0) {
                    *reinterpret_cast<float2*>(Cf + (size_t)r0 * N + c0) = make_float2(o00, o01);
                    *reinterpret_cast<float2*>(Cf + (size_t)r1 * N + c0) = make_float2(o10, o11);
                } else {
                    *reinterpret_cast<__half2*>(Ch + (size_t)r0 * N + c0) = __floats2half2_rn(o00, o01);
                    *reinterpret_cast<__half2*>(Ch + (size_t)r1 * N + c0) = __floats2half2_rn(o10, o11);
                }
            }
        }
    }
}

// ---------------- weight prep ----------------
__global__ __launch_bounds__(256)
void half_copy(const float* __restrict__ in, __half* __restrict__ out, int R, int K, int KP)
{
    int idx = blockIdx.x * blockDim.x + threadIdx.x;
    if (idx >= R * K) return;
    int r = idx / K, k = idx - r * K;
    out[(size_t)r * KP + k] = __float2half_rn(in[idx]);
}

__global__ __launch_bounds__(256)
void half_transpose(const float* __restrict__ in, __half* __restrict__ out, int R, int C, int RP)
{
    __shared__ float t[32][33];
    const int bx = blockIdx.x * 32;
    const int by = blockIdx.y * 32;
    int x = bx + threadIdx.x;
    #pragma unroll
    for (int i = 0; i < 4; i++) {
        int y = by + threadIdx.y + i * 8;
        if (y < R && x < C) t[threadIdx.y + i * 8][threadIdx.x] = in[(size_t)y * C + x];
    }
    __syncthreads();
    x = by + threadIdx.x;
    #pragma unroll
    for (int i = 0; i < 4; i++) {
        int y = bx + threadIdx.y + i * 8;
        if (y < C && x < R)
            out[(size_t)y * RP + x] = __float2half_rn(t[threadIdx.x][threadIdx.y + i * 8]);
    }
}

// ---------------- GRU gates ----------------
__device__ __forceinline__ float sigmoidf(float v) { return 1.f / (1.f + expf(-v)); }

__global__ __launch_bounds__(256)
void gru_gate_kernel(const float* __restrict__ gi, const float* __restrict__ gh,
                     float* __restrict__ h, __half* __restrict__ hr,
                     __half* __restrict__ y, int t)
{
    int idx = blockIdx.x * blockDim.x + threadIdx.x;
    if (idx >= Bb * Hh) return;
    int b = idx / Hh, j = idx - b * Hh;
    const float* gir = gi + (size_t)(b * Ss + t) * G3H;
    const float* ghr = gh + (size_t)b * G3H;
    float ir = gir[j], iz = gir[Hh + j], in = gir[2*Hh + j];
    float hrv = ghr[j], hz = ghr[Hh + j], hn = ghr[2*Hh + j];
    float r = sigmoidf(ir + hrv);
    float z = sigmoidf(iz + hz);
    float n = tanhf(in + r * hn);
    float hold = h[idx];
    float hnew = (1.f - z) * n + z * hold;
    h[idx] = hnew;
    __half hv = __float2half_rn(hnew);
    hr[(size_t)b * HPAD + j] = hv;
    y[(size_t)b * YPAD + t * Hh + j] = hv;
}

__global__ void zero_f32(float* __restrict__ p, int n)
{
    int i = blockIdx.x * blockDim.x + threadIdx.x;
    if (i < n) p[i] = 0.f;
}
__global__ void zero_u32(uint32_t* __restrict__ p, int n)
{
    int i = blockIdx.x * blockDim.x + threadIdx.x;
    if (i < n) p[i] = 0u;
}

// ---------------- launch ----------------
extern "C" void kernel_launch(void* const* d_in, const int* in_sizes, int n_in,
                              void* d_out, int out_size)
{
    const float* x       = (const float*)d_in[0];
    const int*   ei      = (const int*)  d_in[1];
    const float* ef      = (const float*)d_in[2];
    const float* ea      = (const float*)d_in[3];
    const float* Wx      = (const float*)d_in[4];
    const float* We      = (const float*)d_in[5];
    const float* Wf      = (const float*)d_in[6];
    const float* Wedge   = (const float*)d_in[7];
    const float* w_ih    = (const float*)d_in[8];
    const float* w_hh    = (const float*)d_in[9];
    const float* b_ih    = (const float*)d_in[10];
    const float* b_hh    = (const float*)d_in[11];
    const float* mlp_w1  = (const float*)d_in[12];
    const float* mlp_b1  = (const float*)d_in[13];
    const float* mlp_w2  = (const float*)d_in[14];
    const float* mlp_b2  = (const float*)d_in[15];
    float* out = (float*)d_out;

    __half *seq, *wih, *whh, *w1t, *w2t, *hr, *y, *z;
    float *gi, *gh, *h;
    cudaGetSymbolAddress((void**)&seq, g_seq);
    cudaGetSymbolAddress((void**)&wih, g_wih);
    cudaGetSymbolAddress((void**)&whh, g_whh);
    cudaGetSymbolAddress((void**)&w1t, g_w1t);
    cudaGetSymbolAddress((void**)&w2t, g_w2t);
    cudaGetSymbolAddress((void**)&hr,  g_hr);
    cudaGetSymbolAddress((void**)&y,   g_y);
    cudaGetSymbolAddress((void**)&z,   g_z);
    cudaGetSymbolAddress((void**)&gi,  g_gi);
    cudaGetSymbolAddress((void**)&gh,  g_gh);
    cudaGetSymbolAddress((void**)&h,   g_h);

    cudaFuncSetAttribute(h16_gemm_nt<0>,
                         cudaFuncAttributeMaxDynamicSharedMemorySize, GEMM_SMEM_BYTES);
    cudaFuncSetAttribute(h16_gemm_nt<1>,
                         cudaFuncAttributeMaxDynamicSharedMemorySize, GEMM_SMEM_BYTES);

    // 0) weight prep (half copies / transposes; pads stay zero from static init)
    {
        int n = G3H * SEQW;
        half_copy<<<(n + 255) / 256, 256>>>(w_ih, wih, G3H, SEQW, SEQW);
        n = G3H * Hh;
        half_copy<<<(n + 255) / 256, 256>>>(w_hh, whh, G3H, Hh, HPAD);
        dim3 blk(32, 8);
        dim3 g1((MLP1 + 31) / 32, (Ss * Hh + 31) / 32);
        half_transpose<<<g1, blk>>>(mlp_w1, w1t, Ss * Hh, MLP1, YPAD);
        dim3 g2((OUTW + 31) / 32, (MLP1 + 31) / 32);
        half_transpose<<<g2, blk>>>(mlp_w2, w2t, MLP1, OUTW, MLP1);
    }

    // 1) GNN -> seq (half)
    gnn_kernel<<<Bb * Ss, 256>>>(x, ei, ef, ea, Wx, We, Wf, Wedge, seq);

    // 2) gi = seq @ w_ih^T + b_ih  [10240, 2400]
    {
        dim3 grid((G3H + 127) / 128, (Bb * Ss) / 128);
        h16_gemm_nt<0><<<grid, 128, GEMM_SMEM_BYTES>>>(seq, wih, b_ih, gi, nullptr,
                                                       Bb * Ss, G3H, SEQW);
    }

    // 3) GRU recurrence (K padded to 832; hr pad region stays zero)
    zero_f32<<<(Bb * Hh + 255) / 256, 256>>>(h, Bb * Hh);
    {
        int n = (int)((size_t)Bb * HPAD / 2);
        zero_u32<<<(n + 255) / 256, 256>>>((uint32_t*)hr, n);
    }
    for (int t = 0; t < Ss; t++) {
        dim3 grid((G3H + 127) / 128, Bb / 128);
        h16_gemm_nt<0><<<grid, 128, GEMM_SMEM_BYTES>>>(hr, whh, b_hh, gh, nullptr,
                                                       Bb, G3H, HPAD);
        gru_gate_kernel<<<(Bb * Hh + 255) / 256, 256>>>(gi, gh, h, hr, y, t);
    }

    // 4) MLP (K padded to 4032 for layer 1; y pad stays zero)
    {
        dim3 grid((MLP1 + 127) / 128, Bb / 128);
        h16_gemm_nt<1><<<grid, 128, GEMM_SMEM_BYTES>>>(y, w1t, mlp_b1, nullptr, z,
                                                       Bb, MLP1, YPAD);
    }
    {
        dim3 grid((OUTW + 127) / 128, Bb / 128);
        h16_gemm_nt<0><<<grid, 128, GEMM_SMEM_BYTES>>>(z, w2t, mlp_b2, out, nullptr,
                                                       Bb, OUTW, MLP1);
    }
}